// round 2
// baseline (speedup 1.0000x reference)
#include <cuda_runtime.h>
#include <math.h>

#define BB 4
#define CC 256
#define CI 128
#define NP 4096

typedef unsigned long long u64;

// Scratch (device globals: allocation-free rule)
__device__ float g_q[BB * NP * CI];  // theta(x)  : (b, n, o)
__device__ float g_k[BB * NP * CI];  // phi(x)    : (b, m, o)
__device__ float g_v[BB * NP * CI];  // g(x)      : (b, m, o)
__device__ float g_o[BB * NP * CI];  // attention out (b, n, o)

// ---------------- packed fp32x2 helpers (sm_100+) ----------------
__device__ __forceinline__ u64 pack2(float lo, float hi) {
    u64 r;
    asm("mov.b64 %0, {%1, %2};" : "=l"(r) : "f"(lo), "f"(hi));
    return r;
}
__device__ __forceinline__ float2 unpack2(u64 v) {
    float2 f;
    asm("mov.b64 {%0, %1}, %2;" : "=f"(f.x), "=f"(f.y) : "l"(v));
    return f;
}
__device__ __forceinline__ void ffma2(u64& d, u64 a, u64 b) {
    asm("fma.rn.f32x2 %0, %1, %2, %0;" : "+l"(d) : "l"(a), "l"(b));
}
__device__ __forceinline__ u64 fmul2(u64 a, u64 b) {
    u64 d;
    asm("mul.rn.f32x2 %0, %1, %2;" : "=l"(d) : "l"(a), "l"(b));
    return d;
}

// =================================================================
// Kernel 1: QKV projections.
// dst[b, n, o] = sum_c W[o,c] * x[b,c,n] + bias[o]
// Block tile: 128 outputs (o) x 128 pixels (n). 256 threads, micro 8x8.
// grid = (NP/128, BB, 3)   z: 0=theta->g_q, 1=phi->g_k, 2=g->g_v
// =================================================================
__global__ __launch_bounds__(256) void proj_kernel(
    const float* __restrict__ x,
    const float* __restrict__ tw, const float* __restrict__ tb,
    const float* __restrict__ pw, const float* __restrict__ pb,
    const float* __restrict__ gw, const float* __restrict__ gb)
{
    __shared__ float xs[16][132];  // [k][n]
    __shared__ float ws[16][132];  // [k][o]

    const int z  = blockIdx.z;
    const int b  = blockIdx.y;
    const int n0 = blockIdx.x * 128;
    const float* W  = (z == 0) ? tw : (z == 1) ? pw : gw;
    const float* bi = (z == 0) ? tb : (z == 1) ? pb : gb;
    float*      dst = (z == 0) ? g_q : (z == 1) ? g_k : g_v;

    const int t  = threadIdx.x;
    const int tx = t & 15, ty = t >> 4;

    // o = ty + 16*i (i<8), n = 8*tx + 2*j + {0,1} (j<4)
    u64 acc2[8][4];
#pragma unroll
    for (int i = 0; i < 8; i++)
#pragma unroll
        for (int j = 0; j < 4; j++) acc2[i][j] = 0ull;

    const float* xb = x + (size_t)b * CC * NP + n0;

    for (int c0 = 0; c0 < CC; c0 += 16) {
        {   // xs[k][nn]: coalesced float4 over n
            int k   = t >> 5;
            int nn4 = (t & 31) * 4;
            *(float4*)&xs[k][nn4]     = *(const float4*)&xb[(size_t)(c0 + k) * NP + nn4];
            *(float4*)&xs[k + 8][nn4] = *(const float4*)&xb[(size_t)(c0 + k + 8) * NP + nn4];
        }
        {   // ws[k][oo]: W row-major (o, C), contiguous over c
            int k = t & 15, oo = t >> 4;
#pragma unroll
            for (int p = 0; p < 8; p++)
                ws[k][oo + 16 * p] = W[(size_t)(oo + 16 * p) * CC + c0 + k];
        }
        __syncthreads();
#pragma unroll
        for (int k = 0; k < 16; k++) {
            float4 b0 = *(const float4*)&xs[k][8 * tx];
            float4 b1 = *(const float4*)&xs[k][8 * tx + 4];
            u64 bp[4];
            bp[0] = pack2(b0.x, b0.y); bp[1] = pack2(b0.z, b0.w);
            bp[2] = pack2(b1.x, b1.y); bp[3] = pack2(b1.z, b1.w);
#pragma unroll
            for (int i = 0; i < 8; i++) {
                float a  = ws[k][ty + 16 * i];
                u64   a2 = pack2(a, a);
#pragma unroll
                for (int j = 0; j < 4; j++) ffma2(acc2[i][j], a2, bp[j]);
            }
        }
        __syncthreads();
    }

#pragma unroll
    for (int i = 0; i < 8; i++) {
        int   o  = ty + 16 * i;
        float bv = bi[o];
#pragma unroll
        for (int j = 0; j < 4; j++) {
            float2 f = unpack2(acc2[i][j]);
            int    n = n0 + 8 * tx + 2 * j;
            dst[(size_t)(b * NP + n) * CI + o]     = f.x + bv;
            dst[(size_t)(b * NP + n + 1) * CI + o] = f.y + bv;
        }
    }
}

// =================================================================
// Kernel 2: fused flash attention (fp32).
// Per block: batch b, 64 query rows. Loop K/V in 64-row tiles:
//   S = Q K^T  -> online softmax -> O += P V
// Thread map (tx<16, ty<16): S rows r=ty+16i (i<4), S cols m=tx+16j (j<4)
//                            O rows r=ty+16i,       O cols d=8tx..8tx+7
// grid = (NP/64, BB), 256 threads, ~115 KB dynamic smem.
// =================================================================
#define QS 132
#define PS 65

__global__ __launch_bounds__(256) void attn_kernel()
{
    extern __shared__ float smem[];
    float* Qs = smem;             // [64][QS]  (r, k)
    float* Ks = Qs + 64 * QS;     // [64][QS]  (m, k)
    float* Vs = Ks + 64 * QS;     // [64][QS]  (m, d)
    float* Ps = Vs + 64 * QS;     // [64][PS]  (r, m)

    const int b    = blockIdx.y;
    const int row0 = blockIdx.x * 64;
    const int t    = threadIdx.x;
    const int tx   = t & 15, ty = t >> 4;

    const float* gq = g_q + (size_t)b * NP * CI;
    const float* gk = g_k + (size_t)b * NP * CI;
    const float* gv = g_v + (size_t)b * NP * CI;

    // load Q tile (64 x 128)
#pragma unroll
    for (int p = 0; p < 8; p++) {
        int idx = p * 256 + t;
        int r   = idx >> 5;
        int k4  = (idx & 31) * 4;
        *(float4*)&Qs[r * QS + k4] = *(const float4*)&gq[(size_t)(row0 + r) * CI + k4];
    }

    u64   o2[4][4];
    float mrun[4], lrun[4];
#pragma unroll
    for (int i = 0; i < 4; i++) {
        mrun[i] = -INFINITY;
        lrun[i] = 0.0f;
#pragma unroll
        for (int p = 0; p < 4; p++) o2[i][p] = 0ull;
    }

    for (int m0 = 0; m0 < NP; m0 += 64) {
        __syncthreads();  // prior PV done reading Ks/Vs/Ps
#pragma unroll
        for (int p = 0; p < 8; p++) {
            int idx = p * 256 + t;
            int r   = idx >> 5;
            int k4  = (idx & 31) * 4;
            *(float4*)&Ks[r * QS + k4] = *(const float4*)&gk[(size_t)(m0 + r) * CI + k4];
            *(float4*)&Vs[r * QS + k4] = *(const float4*)&gv[(size_t)(m0 + r) * CI + k4];
        }
        __syncthreads();

        // ---- S = Q K^T (pairs over k, folded after the loop) ----
        u64 s2[4][4];
#pragma unroll
        for (int i = 0; i < 4; i++)
#pragma unroll
            for (int j = 0; j < 4; j++) s2[i][j] = 0ull;

#pragma unroll 4
        for (int k = 0; k < CI; k += 4) {
            float4 a4[4], b4[4];
#pragma unroll
            for (int i = 0; i < 4; i++) a4[i] = *(const float4*)&Qs[(ty + 16 * i) * QS + k];
#pragma unroll
            for (int j = 0; j < 4; j++) b4[j] = *(const float4*)&Ks[(tx + 16 * j) * QS + k];
#pragma unroll
            for (int i = 0; i < 4; i++) {
                const u64* ap = (const u64*)&a4[i];
#pragma unroll
                for (int j = 0; j < 4; j++) {
                    const u64* bp = (const u64*)&b4[j];
                    ffma2(s2[i][j], ap[0], bp[0]);
                    ffma2(s2[i][j], ap[1], bp[1]);
                }
            }
        }

        // ---- online softmax (row state replicated across the 16 lanes of a row) ----
#pragma unroll
        for (int i = 0; i < 4; i++) {
            float s[4];
#pragma unroll
            for (int j = 0; j < 4; j++) {
                float2 f = unpack2(s2[i][j]);
                s[j] = f.x + f.y;
            }
            float tmax = fmaxf(fmaxf(s[0], s[1]), fmaxf(s[2], s[3]));
#pragma unroll
            for (int d = 1; d < 16; d <<= 1)
                tmax = fmaxf(tmax, __shfl_xor_sync(0xffffffffu, tmax, d));
            float mnew = fmaxf(mrun[i], tmax);
            float corr = __expf(mrun[i] - mnew);
            mrun[i] = mnew;

            float ssum = 0.0f;
#pragma unroll
            for (int j = 0; j < 4; j++) {
                float e = __expf(s[j] - mnew);
                Ps[(ty + 16 * i) * PS + tx + 16 * j] = e;
                ssum += e;
            }
#pragma unroll
            for (int d = 1; d < 16; d <<= 1)
                ssum += __shfl_xor_sync(0xffffffffu, ssum, d);
            lrun[i] = lrun[i] * corr + ssum;

            u64 c2 = pack2(corr, corr);
#pragma unroll
            for (int p = 0; p < 4; p++) o2[i][p] = fmul2(o2[i][p], c2);
        }
        __syncthreads();

        // ---- O += P V ----
#pragma unroll 8
        for (int m = 0; m < 64; m++) {
            float4 v0 = *(const float4*)&Vs[m * QS + 8 * tx];
            float4 v1 = *(const float4*)&Vs[m * QS + 8 * tx + 4];
            const u64* vp0 = (const u64*)&v0;
            const u64* vp1 = (const u64*)&v1;
#pragma unroll
            for (int i = 0; i < 4; i++) {
                float pv = Ps[(ty + 16 * i) * PS + m];
                u64   p2 = pack2(pv, pv);
                ffma2(o2[i][0], p2, vp0[0]);
                ffma2(o2[i][1], p2, vp0[1]);
                ffma2(o2[i][2], p2, vp1[0]);
                ffma2(o2[i][3], p2, vp1[1]);
            }
        }
    }

    // finalize: O /= l, store (b, n, o)
    float* go = g_o + (size_t)b * NP * CI;
#pragma unroll
    for (int i = 0; i < 4; i++) {
        float  inv = 1.0f / lrun[i];
        float2 f0 = unpack2(o2[i][0]);
        float2 f1 = unpack2(o2[i][1]);
        float2 f2 = unpack2(o2[i][2]);
        float2 f3 = unpack2(o2[i][3]);
        float4 w0 = make_float4(f0.x * inv, f0.y * inv, f1.x * inv, f1.y * inv);
        float4 w1 = make_float4(f2.x * inv, f2.y * inv, f3.x * inv, f3.y * inv);
        size_t base = (size_t)(row0 + ty + 16 * i) * CI + 8 * tx;
        *(float4*)&go[base]     = w0;
        *(float4*)&go[base + 4] = w1;
    }
}

// =================================================================
// Kernel 3: output projection + bias + residual.
// out[b,c,n] = sum_o w_w[c,o]*g_o[b,n,o] + w_b[c] + x[b,c,n]
// Block tile: 64 c x 128 n. grid = (NP/128, CC/64, BB)
// =================================================================
__global__ __launch_bounds__(256) void outproj_kernel(
    const float* __restrict__ x,
    const float* __restrict__ ww, const float* __restrict__ wb,
    float* __restrict__ out)
{
    __shared__ float os[16][132];  // [o-chunk][n]
    __shared__ float ws[16][68];   // [o-chunk][c]

    const int b  = blockIdx.z;
    const int c0 = blockIdx.y * 64;
    const int n0 = blockIdx.x * 128;
    const int t  = threadIdx.x, tx = t & 15, ty = t >> 4;

    // c = ty + 16*i (i<4), n = 8*tx + 2*j + {0,1} (j<4)
    u64 acc2[4][4];
#pragma unroll
    for (int i = 0; i < 4; i++)
#pragma unroll
        for (int j = 0; j < 4; j++) acc2[i][j] = 0ull;

    const float* ob = g_o + (size_t)b * NP * CI;

    for (int o0 = 0; o0 < CI; o0 += 16) {
        {   // os[k][nn] transposed from pixel-major g_o
            int k4 = (t & 3) * 4;
            int nn = t >> 2;
#pragma unroll
            for (int h = 0; h < 2; h++) {
                float4 v = *(const float4*)&ob[(size_t)(n0 + nn + 64 * h) * CI + o0 + k4];
                os[k4 + 0][nn + 64 * h] = v.x;
                os[k4 + 1][nn + 64 * h] = v.y;
                os[k4 + 2][nn + 64 * h] = v.z;
                os[k4 + 3][nn + 64 * h] = v.w;
            }
        }
        {   // ws[k][cc] from w_w (C, CI) row-major
            int k = t & 15, cc = t >> 4;
#pragma unroll
            for (int p = 0; p < 4; p++)
                ws[k][cc + 16 * p] = ww[(size_t)(c0 + cc + 16 * p) * CI + o0 + k];
        }
        __syncthreads();
#pragma unroll
        for (int k = 0; k < 16; k++) {
            float4 b0 = *(const float4*)&os[k][8 * tx];
            float4 b1 = *(const float4*)&os[k][8 * tx + 4];
            u64 bp[4];
            bp[0] = pack2(b0.x, b0.y); bp[1] = pack2(b0.z, b0.w);
            bp[2] = pack2(b1.x, b1.y); bp[3] = pack2(b1.z, b1.w);
#pragma unroll
            for (int i = 0; i < 4; i++) {
                float a  = ws[k][ty + 16 * i];
                u64   a2 = pack2(a, a);
#pragma unroll
                for (int j = 0; j < 4; j++) ffma2(acc2[i][j], a2, bp[j]);
            }
        }
        __syncthreads();
    }

#pragma unroll
    for (int i = 0; i < 4; i++) {
        int    c    = c0 + ty + 16 * i;
        float  bv   = wb[c];
        size_t base = ((size_t)b * CC + c) * NP + n0 + 8 * tx;
        float4 xv0  = *(const float4*)&x[base];
        float4 xv1  = *(const float4*)&x[base + 4];
        float2 f0 = unpack2(acc2[i][0]);
        float2 f1 = unpack2(acc2[i][1]);
        float2 f2 = unpack2(acc2[i][2]);
        float2 f3 = unpack2(acc2[i][3]);
        float4 r0 = make_float4(f0.x + bv + xv0.x, f0.y + bv + xv0.y,
                                f1.x + bv + xv0.z, f1.y + bv + xv0.w);
        float4 r1 = make_float4(f2.x + bv + xv1.x, f2.y + bv + xv1.y,
                                f3.x + bv + xv1.z, f3.y + bv + xv1.w);
        *(float4*)&out[base]     = r0;
        *(float4*)&out[base + 4] = r1;
    }
}

// =================================================================
extern "C" void kernel_launch(void* const* d_in, const int* in_sizes, int n_in,
                              void* d_out, int out_size)
{
    const float* x  = (const float*)d_in[0];
    const float* tw = (const float*)d_in[1];
    const float* tb = (const float*)d_in[2];
    const float* pw = (const float*)d_in[3];
    const float* pb = (const float*)d_in[4];
    const float* gw = (const float*)d_in[5];
    const float* gb = (const float*)d_in[6];
    const float* ww = (const float*)d_in[7];
    const float* wb = (const float*)d_in[8];
    float* out = (float*)d_out;

    const int smem_attn = (3 * 64 * QS + 64 * PS) * (int)sizeof(float);
    cudaFuncSetAttribute(attn_kernel, cudaFuncAttributeMaxDynamicSharedMemorySize, smem_attn);

    proj_kernel<<<dim3(NP / 128, BB, 3), 256>>>(x, tw, tb, pw, pb, gw, gb);
    attn_kernel<<<dim3(NP / 64, BB), 256, smem_attn>>>();
    outproj_kernel<<<dim3(NP / 128, CC / 64, BB), 256>>>(x, ww, wb, out);
}

// round 4
// speedup vs baseline: 3.6809x; 3.6809x over previous
#include <cuda_runtime.h>
#include <cuda_fp16.h>
#include <math.h>
#include <stdint.h>

#define BB 4
#define CC 256
#define CI 128
#define NP 4096
#define LOG2E 1.4426950408889634f

typedef unsigned long long u64;
typedef unsigned int u32;

// Scratch (device globals: allocation-free rule)
__device__ __half g_qh[BB * NP * CI];  // theta(x)*log2e hi : (b, n, o)
__device__ __half g_ql[BB * NP * CI];  // theta(x)*log2e lo
__device__ __half g_kh[BB * NP * CI];  // phi(x) hi : (b, m, o)
__device__ __half g_kl[BB * NP * CI];  // phi(x) lo
__device__ __half g_vt[BB * CI * NP];  // g(x) transposed : (b, o, m)
__device__ float  g_o [BB * NP * CI];  // attention out (b, n, o)

// ---------------- packed fp32x2 helpers ----------------
__device__ __forceinline__ u64 pack2(float lo, float hi) {
    u64 r;
    asm("mov.b64 %0, {%1, %2};" : "=l"(r) : "f"(lo), "f"(hi));
    return r;
}
__device__ __forceinline__ float2 unpack2(u64 v) {
    float2 f;
    asm("mov.b64 {%0, %1}, %2;" : "=f"(f.x), "=f"(f.y) : "l"(v));
    return f;
}
__device__ __forceinline__ void ffma2(u64& d, u64 a, u64 b) {
    asm("fma.rn.f32x2 %0, %1, %2, %0;" : "+l"(d) : "l"(a), "l"(b));
}
__device__ __forceinline__ float ex2(float x) {
    float y;
    asm("ex2.approx.ftz.f32 %0, %1;" : "=f"(y) : "f"(x));
    return y;
}
__device__ __forceinline__ u32 smem_u32(const void* p) {
    u32 a;
    asm("{ .reg .u64 t; cvta.to.shared.u64 t, %1; cvt.u32.u64 %0, t; }" : "=r"(a) : "l"(p));
    return a;
}

// ---------------- mma.sync / ldmatrix / cp.async ----------------
__device__ __forceinline__ void ldm4(u32& r0, u32& r1, u32& r2, u32& r3, u32 addr) {
    asm volatile("ldmatrix.sync.aligned.m8n8.x4.shared.b16 {%0,%1,%2,%3}, [%4];"
                 : "=r"(r0), "=r"(r1), "=r"(r2), "=r"(r3) : "r"(addr));
}
__device__ __forceinline__ void mma16816(float* c, u32 a0, u32 a1, u32 a2, u32 a3,
                                         u32 b0, u32 b1) {
    asm volatile(
        "mma.sync.aligned.m16n8k16.row.col.f32.f16.f16.f32 "
        "{%0,%1,%2,%3}, {%4,%5,%6,%7}, {%8,%9}, {%0,%1,%2,%3};"
        : "+f"(c[0]), "+f"(c[1]), "+f"(c[2]), "+f"(c[3])
        : "r"(a0), "r"(a1), "r"(a2), "r"(a3), "r"(b0), "r"(b1));
}
__device__ __forceinline__ void cpa(u32 s, const void* g) {
    asm volatile("cp.async.cg.shared.global [%0], [%1], 16;" :: "r"(s), "l"(g));
}
#define CP_COMMIT() asm volatile("cp.async.commit_group;")
#define CP_WAIT1()  asm volatile("cp.async.wait_group 1;")

// =================================================================
// Kernel 1: QKV projections (fp32 compute, fp16 hi/lo outputs).
// =================================================================
__global__ __launch_bounds__(256) void proj_kernel(
    const float* __restrict__ x,
    const float* __restrict__ tw, const float* __restrict__ tb,
    const float* __restrict__ pw, const float* __restrict__ pb,
    const float* __restrict__ gw, const float* __restrict__ gb)
{
    __shared__ float xs[16][132];  // [k][n]
    __shared__ float ws[16][132];  // [k][o]

    const int z  = blockIdx.z;
    const int b  = blockIdx.y;
    const int n0 = blockIdx.x * 128;
    const float* W  = (z == 0) ? tw : (z == 1) ? pw : gw;
    const float* bi = (z == 0) ? tb : (z == 1) ? pb : gb;

    const int t  = threadIdx.x;
    const int tx = t & 15, ty = t >> 4;

    // o = 8*ty + i (i<8), n = 8*tx + 2*j + {0,1} (j<4)
    u64 acc2[8][4];
#pragma unroll
    for (int i = 0; i < 8; i++)
#pragma unroll
        for (int j = 0; j < 4; j++) acc2[i][j] = 0ull;

    const float* xb = x + (size_t)b * CC * NP + n0;

    for (int c0 = 0; c0 < CC; c0 += 16) {
        {
            int k   = t >> 5;
            int nn4 = (t & 31) * 4;
            *(float4*)&xs[k][nn4]     = *(const float4*)&xb[(size_t)(c0 + k) * NP + nn4];
            *(float4*)&xs[k + 8][nn4] = *(const float4*)&xb[(size_t)(c0 + k + 8) * NP + nn4];
        }
        {
            int k = t & 15, oo = t >> 4;
#pragma unroll
            for (int p = 0; p < 8; p++)
                ws[k][oo + 16 * p] = W[(size_t)(oo + 16 * p) * CC + c0 + k];
        }
        __syncthreads();
#pragma unroll
        for (int k = 0; k < 16; k++) {
            float4 b0 = *(const float4*)&xs[k][8 * tx];
            float4 b1 = *(const float4*)&xs[k][8 * tx + 4];
            u64 bp[4];
            bp[0] = pack2(b0.x, b0.y); bp[1] = pack2(b0.z, b0.w);
            bp[2] = pack2(b1.x, b1.y); bp[3] = pack2(b1.z, b1.w);
            float4 w0 = *(const float4*)&ws[k][8 * ty];
            float4 w1 = *(const float4*)&ws[k][8 * ty + 4];
            float wa[8] = {w0.x, w0.y, w0.z, w0.w, w1.x, w1.y, w1.z, w1.w};
#pragma unroll
            for (int i = 0; i < 8; i++) {
                u64 a2 = pack2(wa[i], wa[i]);
#pragma unroll
                for (int j = 0; j < 4; j++) ffma2(acc2[i][j], a2, bp[j]);
            }
        }
        __syncthreads();
    }

    if (z == 2) {
        // V transposed: (b, o, m), fp16, contiguous over m
#pragma unroll
        for (int i = 0; i < 8; i++) {
            int   o  = 8 * ty + i;
            float bv = bi[o];
#pragma unroll
            for (int j = 0; j < 4; j++) {
                float2 f = unpack2(acc2[i][j]);
                int    n = n0 + 8 * tx + 2 * j;
                __half2 hv = __floats2half2_rn(f.x + bv, f.y + bv);
                *(__half2*)&g_vt[((size_t)b * CI + o) * NP + n] = hv;
            }
        }
    } else {
        // Q/K: (b, n, o) fp16 hi/lo, packed uint4 stores over o
        __half* dh = (z == 0) ? g_qh : g_kh;
        __half* dl = (z == 0) ? g_ql : g_kl;
        const float sc = (z == 0) ? LOG2E : 1.0f;
#pragma unroll
        for (int jj = 0; jj < 8; jj++) {
            int n = n0 + 8 * tx + jj;
            __half hs[8], ls[8];
#pragma unroll
            for (int i = 0; i < 8; i++) {
                float2 f = unpack2(acc2[i][jj >> 1]);
                float  v = (((jj & 1) ? f.y : f.x) + bi[8 * ty + i]) * sc;
                __half h = __float2half_rn(v);
                hs[i] = h;
                ls[i] = __float2half_rn(v - __half2float(h));
            }
            size_t base = ((size_t)b * NP + n) * CI + 8 * ty;
            *(uint4*)&dh[base] = *(uint4*)hs;
            *(uint4*)&dl[base] = *(uint4*)ls;
        }
    }
}

// =================================================================
// Kernel 2: flash attention on mma.sync.m16n8k16 (fp16 in, f32 accum).
// CTA: 128 q-rows, 8 warps x 16 rows. KV tiles of 64, double-buffered
// via cp.async. S and O live entirely in registers.
// =================================================================
#define KQSTRIDE 272   // bytes per row: 136 halves (128 + 8 pad) -> 4 mod 32 words
#define VSTRIDE  144   // bytes per row: 72 halves (64 + 8 pad)
#define OFF_Q    0
#define OFF_QL   34816
#define OFF_K    69632                 // + stage*34816 (hi at +0, lo at +17408)
#define OFF_V    139264                // + stage*18432
#define SMEM_ATTN 176128

__device__ __forceinline__ void load_kv(u32 s32, int stage, int m0,
                                        const __half* gkh, const __half* gkl,
                                        const __half* gvt, int t)
{
    u32 kh = s32 + OFF_K + stage * 34816;
    u32 kl = kh + 17408;
    u32 vv = s32 + OFF_V + stage * 18432;
#pragma unroll
    for (int i = 0; i < 4; i++) {
        int id  = i * 256 + t;
        int row = id >> 4, c = id & 15;
        cpa(kh + row * KQSTRIDE + c * 16, gkh + (size_t)(m0 + row) * CI + c * 8);
        cpa(kl + row * KQSTRIDE + c * 16, gkl + (size_t)(m0 + row) * CI + c * 8);
        int vrow = id >> 3, vc = id & 7;
        cpa(vv + vrow * VSTRIDE + vc * 16, gvt + (size_t)vrow * NP + m0 + vc * 8);
    }
}

__global__ __launch_bounds__(256, 1) void attn_kernel()
{
    extern __shared__ __align__(128) char smem[];
    const u32 s32  = smem_u32(smem);
    const int t    = threadIdx.x;
    const int lane = t & 31;
    const int wr   = (t >> 5) * 16;          // warp's q-row base within CTA
    const int b    = blockIdx.y;
    const int row0 = blockIdx.x * 128;

    // ldmatrix lane addressing: row = base + (lane&15), colB = base + (lane>>4)*16
    const int lrow = lane & 15;
    const int lcol = (lane >> 4) * 16;
    const int g    = lane >> 2;              // row within 16-row tile (and +8)
    const int c2   = (lane & 3) * 2;         // col pair within 8-col tile

    const __half* gqh = g_qh + ((size_t)b * NP + row0) * CI;
    const __half* gql = g_ql + ((size_t)b * NP + row0) * CI;
    const __half* gkh = g_kh + (size_t)b * NP * CI;
    const __half* gkl = g_kl + (size_t)b * NP * CI;
    const __half* gvt = g_vt + (size_t)b * CI * NP;

    // ---- prologue: Q (hi+lo) + tile0 in group0, tile1 in group1 ----
#pragma unroll
    for (int i = 0; i < 8; i++) {
        int id = i * 256 + t;
        int row = id >> 4, c = id & 15;
        cpa(s32 + OFF_Q  + row * KQSTRIDE + c * 16, gqh + (size_t)row * CI + c * 8);
        cpa(s32 + OFF_QL + row * KQSTRIDE + c * 16, gql + (size_t)row * CI + c * 8);
    }
    load_kv(s32, 0, 0, gkh, gkl, gvt, t);
    CP_COMMIT();
    load_kv(s32, 1, 64, gkh, gkl, gvt, t);
    CP_COMMIT();

    float o[16][4];
#pragma unroll
    for (int j = 0; j < 16; j++)
#pragma unroll
        for (int q = 0; q < 4; q++) o[j][q] = 0.0f;
    float mrun0 = -1e30f, mrun1 = -1e30f, lrun0 = 0.0f, lrun1 = 0.0f;

    for (int tile = 0; tile < NP / 64; tile++) {
        const int stage = tile & 1;
        CP_WAIT1();
        __syncthreads();

        const u32 kh0 = s32 + OFF_K + stage * 34816;
        const u32 kl0 = kh0 + 17408;
        const u32 vv0 = s32 + OFF_V + stage * 18432;

        // ---- S = Qhi.Khi^T + Qlo.Khi^T + Qhi.Klo^T ----
        float s[8][4];
#pragma unroll
        for (int j = 0; j < 8; j++)
#pragma unroll
            for (int q = 0; q < 4; q++) s[j][q] = 0.0f;

#pragma unroll
        for (int kc = 0; kc < 8; kc++) {
            u32 qh[4], ql[4];
            ldm4(qh[0], qh[1], qh[2], qh[3],
                 s32 + OFF_Q  + (wr + lrow) * KQSTRIDE + kc * 32 + lcol);
            ldm4(ql[0], ql[1], ql[2], ql[3],
                 s32 + OFF_QL + (wr + lrow) * KQSTRIDE + kc * 32 + lcol);
#pragma unroll
            for (int nb = 0; nb < 4; nb++) {
                u32 k0, k1, k2, k3;
                ldm4(k0, k1, k2, k3,
                     kh0 + (nb * 16 + lrow) * KQSTRIDE + kc * 32 + lcol);
                mma16816(s[2 * nb],     qh[0], qh[1], qh[2], qh[3], k0, k2);
                mma16816(s[2 * nb + 1], qh[0], qh[1], qh[2], qh[3], k1, k3);
                mma16816(s[2 * nb],     ql[0], ql[1], ql[2], ql[3], k0, k2);
                mma16816(s[2 * nb + 1], ql[0], ql[1], ql[2], ql[3], k1, k3);
                ldm4(k0, k1, k2, k3,
                     kl0 + (nb * 16 + lrow) * KQSTRIDE + kc * 32 + lcol);
                mma16816(s[2 * nb],     qh[0], qh[1], qh[2], qh[3], k0, k2);
                mma16816(s[2 * nb + 1], qh[0], qh[1], qh[2], qh[3], k1, k3);
            }
        }

        // ---- online softmax (rows g and g+8; 4-lane shuffles) ----
        float mx0 = fmaxf(s[0][0], s[0][1]);
        float mx1 = fmaxf(s[0][2], s[0][3]);
#pragma unroll
        for (int j = 1; j < 8; j++) {
            mx0 = fmaxf(mx0, fmaxf(s[j][0], s[j][1]));
            mx1 = fmaxf(mx1, fmaxf(s[j][2], s[j][3]));
        }
        mx0 = fmaxf(mx0, __shfl_xor_sync(0xffffffffu, mx0, 1));
        mx0 = fmaxf(mx0, __shfl_xor_sync(0xffffffffu, mx0, 2));
        mx1 = fmaxf(mx1, __shfl_xor_sync(0xffffffffu, mx1, 1));
        mx1 = fmaxf(mx1, __shfl_xor_sync(0xffffffffu, mx1, 2));
        float mnew0 = fmaxf(mrun0, mx0);
        float mnew1 = fmaxf(mrun1, mx1);
        float corr0 = ex2(mrun0 - mnew0);
        float corr1 = ex2(mrun1 - mnew1);
        mrun0 = mnew0; mrun1 = mnew1;

        float ls0 = 0.0f, ls1 = 0.0f;
        u32 p[8][2];
#pragma unroll
        for (int j = 0; j < 8; j++) {
            float e0 = ex2(s[j][0] - mnew0);
            float e1 = ex2(s[j][1] - mnew0);
            float e2 = ex2(s[j][2] - mnew1);
            float e3 = ex2(s[j][3] - mnew1);
            ls0 += e0 + e1;
            ls1 += e2 + e3;
            __half2 h01 = __floats2half2_rn(e0, e1);
            __half2 h23 = __floats2half2_rn(e2, e3);
            p[j][0] = *(u32*)&h01;
            p[j][1] = *(u32*)&h23;
        }
        ls0 += __shfl_xor_sync(0xffffffffu, ls0, 1);
        ls0 += __shfl_xor_sync(0xffffffffu, ls0, 2);
        ls1 += __shfl_xor_sync(0xffffffffu, ls1, 1);
        ls1 += __shfl_xor_sync(0xffffffffu, ls1, 2);
        lrun0 = lrun0 * corr0 + ls0;
        lrun1 = lrun1 * corr1 + ls1;

        // rescale O only when the running max actually moved
        if (__any_sync(0xffffffffu, (corr0 < 0.99999f) | (corr1 < 0.99999f))) {
#pragma unroll
            for (int j = 0; j < 16; j++) {
                o[j][0] *= corr0; o[j][1] *= corr0;
                o[j][2] *= corr1; o[j][3] *= corr1;
            }
        }

        // ---- O += P.V ----
#pragma unroll
        for (int kc2 = 0; kc2 < 4; kc2++) {
            u32 a0 = p[2 * kc2][0], a1 = p[2 * kc2][1];
            u32 a2 = p[2 * kc2 + 1][0], a3 = p[2 * kc2 + 1][1];
#pragma unroll
            for (int dg = 0; dg < 8; dg++) {
                u32 v0, v1, v2, v3;
                ldm4(v0, v1, v2, v3,
                     vv0 + (dg * 16 + lrow) * VSTRIDE + kc2 * 32 + lcol);
                mma16816(o[2 * dg],     a0, a1, a2, a3, v0, v2);
                mma16816(o[2 * dg + 1], a0, a1, a2, a3, v1, v3);
            }
        }

        // ---- prefetch tile+2 into this stage (after all warps done) ----
        __syncthreads();
        int m2 = (tile + 2) * 64;
        if (m2 < NP) load_kv(s32, stage, m2, gkh, gkl, gvt, t);
        CP_COMMIT();
    }

    // ---- finalize: O /= l, store f32 to g_o (b, n, o) ----
    float inv0 = 1.0f / lrun0;
    float inv1 = 1.0f / lrun1;
    float* go = g_o + ((size_t)b * NP + row0 + wr) * CI;
#pragma unroll
    for (int j = 0; j < 16; j++) {
        *(float2*)&go[(size_t)g * CI + j * 8 + c2] =
            make_float2(o[j][0] * inv0, o[j][1] * inv0);
        *(float2*)&go[(size_t)(g + 8) * CI + j * 8 + c2] =
            make_float2(o[j][2] * inv1, o[j][3] * inv1);
    }
}

// =================================================================
// Kernel 3: output projection + bias + residual.
// =================================================================
__global__ __launch_bounds__(256) void outproj_kernel(
    const float* __restrict__ x,
    const float* __restrict__ ww, const float* __restrict__ wb,
    float* __restrict__ out)
{
    __shared__ float os[16][132];  // [o-chunk][n]
    __shared__ float ws[16][68];   // [o-chunk][c]

    const int b  = blockIdx.z;
    const int c0 = blockIdx.y * 64;
    const int n0 = blockIdx.x * 128;
    const int t  = threadIdx.x, tx = t & 15, ty = t >> 4;

    u64 acc2[4][4];
#pragma unroll
    for (int i = 0; i < 4; i++)
#pragma unroll
        for (int j = 0; j < 4; j++) acc2[i][j] = 0ull;

    const float* ob = g_o + (size_t)b * NP * CI;

    for (int o0 = 0; o0 < CI; o0 += 16) {
        {
            int k4 = (t & 3) * 4;
            int nn = t >> 2;
#pragma unroll
            for (int hh = 0; hh < 2; hh++) {
                float4 v = *(const float4*)&ob[(size_t)(n0 + nn + 64 * hh) * CI + o0 + k4];
                os[k4 + 0][nn + 64 * hh] = v.x;
                os[k4 + 1][nn + 64 * hh] = v.y;
                os[k4 + 2][nn + 64 * hh] = v.z;
                os[k4 + 3][nn + 64 * hh] = v.w;
            }
        }
        {
            int k = t & 15, cc = t >> 4;
#pragma unroll
            for (int p = 0; p < 4; p++)
                ws[k][cc + 16 * p] = ww[(size_t)(c0 + cc + 16 * p) * CI + o0 + k];
        }
        __syncthreads();
#pragma unroll
        for (int k = 0; k < 16; k++) {
            float4 b0 = *(const float4*)&os[k][8 * tx];
            float4 b1 = *(const float4*)&os[k][8 * tx + 4];
            u64 bp[4];
            bp[0] = pack2(b0.x, b0.y); bp[1] = pack2(b0.z, b0.w);
            bp[2] = pack2(b1.x, b1.y); bp[3] = pack2(b1.z, b1.w);
            float4 wv = *(const float4*)&ws[k][4 * ty];
            float wa[4] = {wv.x, wv.y, wv.z, wv.w};
#pragma unroll
            for (int i = 0; i < 4; i++) {
                u64 a2 = pack2(wa[i], wa[i]);
#pragma unroll
                for (int j = 0; j < 4; j++) ffma2(acc2[i][j], a2, bp[j]);
            }
        }
        __syncthreads();
    }

#pragma unroll
    for (int i = 0; i < 4; i++) {
        int    c    = c0 + 4 * ty + i;
        float  bv   = wb[c];
        size_t base = ((size_t)b * CC + c) * NP + n0 + 8 * tx;
        float4 xv0  = *(const float4*)&x[base];
        float4 xv1  = *(const float4*)&x[base + 4];
        float2 f0 = unpack2(acc2[i][0]);
        float2 f1 = unpack2(acc2[i][1]);
        float2 f2 = unpack2(acc2[i][2]);
        float2 f3 = unpack2(acc2[i][3]);
        float4 r0 = make_float4(f0.x + bv + xv0.x, f0.y + bv + xv0.y,
                                f1.x + bv + xv0.z, f1.y + bv + xv0.w);
        float4 r1 = make_float4(f2.x + bv + xv1.x, f2.y + bv + xv1.y,
                                f3.x + bv + xv1.z, f3.y + bv + xv1.w);
        *(float4*)&out[base]     = r0;
        *(float4*)&out[base + 4] = r1;
    }
}

// =================================================================
extern "C" void kernel_launch(void* const* d_in, const int* in_sizes, int n_in,
                              void* d_out, int out_size)
{
    const float* x  = (const float*)d_in[0];
    const float* tw = (const float*)d_in[1];
    const float* tb = (const float*)d_in[2];
    const float* pw = (const float*)d_in[3];
    const float* pb = (const float*)d_in[4];
    const float* gw = (const float*)d_in[5];
    const float* gb = (const float*)d_in[6];
    const float* ww = (const float*)d_in[7];
    const float* wb = (const float*)d_in[8];
    float* out = (float*)d_out;

    cudaFuncSetAttribute(attn_kernel, cudaFuncAttributeMaxDynamicSharedMemorySize, SMEM_ATTN);

    proj_kernel<<<dim3(NP / 128, BB, 3), 256>>>(x, tw, tb, pw, pb, gw, gb);
    attn_kernel<<<dim3(NP / 128, BB), 256, SMEM_ATTN>>>();
    outproj_kernel<<<dim3(NP / 128, CC / 64, BB), 256>>>(x, ww, wb, out);
}

// round 5
// speedup vs baseline: 4.1065x; 1.1156x over previous
#include <cuda_runtime.h>
#include <cuda_fp16.h>
#include <math.h>
#include <stdint.h>

#define BB 4
#define CC 256
#define CI 128
#define NP 4096
#define LOG2E 1.4426950408889634f

typedef unsigned long long u64;
typedef unsigned int u32;

// Scratch (device globals: allocation-free rule)
__device__ __half g_qh[BB * NP * CI];  // theta(x)*log2e hi         : (b, n, o)
__device__ __half g_qc[BB * NP * CI];  // qh/64 + ql (correction)   : (b, n, o)
__device__ __half g_kh[BB * NP * CI];  // phi(x) hi                 : (b, m, o)
__device__ __half g_kc[BB * NP * CI];  // kh + 64*kl (correction)   : (b, m, o)
__device__ __half g_vt[BB * CI * NP];  // g(x) transposed           : (b, o, m)
__device__ float  g_po[2 * BB * NP * CI];  // unnormalized partial O per kv-split
__device__ float  g_pm[2 * BB * NP];       // partial running max (log2 domain)
__device__ float  g_pl[2 * BB * NP];       // partial running sum
__device__ float  g_o [BB * NP * CI];      // merged attention out (b, n, o)

// ---------------- packed fp32x2 helpers ----------------
__device__ __forceinline__ u64 pack2(float lo, float hi) {
    u64 r;
    asm("mov.b64 %0, {%1, %2};" : "=l"(r) : "f"(lo), "f"(hi));
    return r;
}
__device__ __forceinline__ float2 unpack2(u64 v) {
    float2 f;
    asm("mov.b64 {%0, %1}, %2;" : "=f"(f.x), "=f"(f.y) : "l"(v));
    return f;
}
__device__ __forceinline__ void ffma2(u64& d, u64 a, u64 b) {
    asm("fma.rn.f32x2 %0, %1, %2, %0;" : "+l"(d) : "l"(a), "l"(b));
}
__device__ __forceinline__ float ex2(float x) {
    float y;
    asm("ex2.approx.ftz.f32 %0, %1;" : "=f"(y) : "f"(x));
    return y;
}
__device__ __forceinline__ u32 smem_u32(const void* p) {
    u32 a;
    asm("{ .reg .u64 t; cvta.to.shared.u64 t, %1; cvt.u32.u64 %0, t; }" : "=r"(a) : "l"(p));
    return a;
}

// ---------------- mma.sync / ldmatrix / cp.async ----------------
__device__ __forceinline__ void ldm4(u32& r0, u32& r1, u32& r2, u32& r3, u32 addr) {
    asm volatile("ldmatrix.sync.aligned.m8n8.x4.shared.b16 {%0,%1,%2,%3}, [%4];"
                 : "=r"(r0), "=r"(r1), "=r"(r2), "=r"(r3) : "r"(addr));
}
__device__ __forceinline__ void mma16816(float* c, u32 a0, u32 a1, u32 a2, u32 a3,
                                         u32 b0, u32 b1) {
    asm volatile(
        "mma.sync.aligned.m16n8k16.row.col.f32.f16.f16.f32 "
        "{%0,%1,%2,%3}, {%4,%5,%6,%7}, {%8,%9}, {%0,%1,%2,%3};"
        : "+f"(c[0]), "+f"(c[1]), "+f"(c[2]), "+f"(c[3])
        : "r"(a0), "r"(a1), "r"(a2), "r"(a3), "r"(b0), "r"(b1));
}
__device__ __forceinline__ void cpa(u32 s, const void* g) {
    asm volatile("cp.async.cg.shared.global [%0], [%1], 16;" :: "r"(s), "l"(g));
}
#define CP_COMMIT() asm volatile("cp.async.commit_group;")
#define CP_WAIT1()  asm volatile("cp.async.wait_group 1;")

// =================================================================
// Kernel 1: QKV projections (fp32 FFMA compute at roofline).
// z: 0=theta -> (g_qh, g_qc) with *log2e, 1=phi -> (g_kh, g_kc),
// 2=g -> g_vt (fp16, transposed).
// =================================================================
__global__ __launch_bounds__(256) void proj_kernel(
    const float* __restrict__ x,
    const float* __restrict__ tw, const float* __restrict__ tb,
    const float* __restrict__ pw, const float* __restrict__ pb,
    const float* __restrict__ gw, const float* __restrict__ gb)
{
    __shared__ float xs[16][132];
    __shared__ float ws[16][132];

    const int z  = blockIdx.z;
    const int b  = blockIdx.y;
    const int n0 = blockIdx.x * 128;
    const float* W  = (z == 0) ? tw : (z == 1) ? pw : gw;
    const float* bi = (z == 0) ? tb : (z == 1) ? pb : gb;

    const int t  = threadIdx.x;
    const int tx = t & 15, ty = t >> 4;

    u64 acc2[8][4];
#pragma unroll
    for (int i = 0; i < 8; i++)
#pragma unroll
        for (int j = 0; j < 4; j++) acc2[i][j] = 0ull;

    const float* xb = x + (size_t)b * CC * NP + n0;

    for (int c0 = 0; c0 < CC; c0 += 16) {
        {
            int k   = t >> 5;
            int nn4 = (t & 31) * 4;
            *(float4*)&xs[k][nn4]     = *(const float4*)&xb[(size_t)(c0 + k) * NP + nn4];
            *(float4*)&xs[k + 8][nn4] = *(const float4*)&xb[(size_t)(c0 + k + 8) * NP + nn4];
        }
        {
            int k = t & 15, oo = t >> 4;
#pragma unroll
            for (int p = 0; p < 8; p++)
                ws[k][oo + 16 * p] = W[(size_t)(oo + 16 * p) * CC + c0 + k];
        }
        __syncthreads();
#pragma unroll
        for (int k = 0; k < 16; k++) {
            float4 b0 = *(const float4*)&xs[k][8 * tx];
            float4 b1 = *(const float4*)&xs[k][8 * tx + 4];
            u64 bp[4];
            bp[0] = pack2(b0.x, b0.y); bp[1] = pack2(b0.z, b0.w);
            bp[2] = pack2(b1.x, b1.y); bp[3] = pack2(b1.z, b1.w);
            float4 w0 = *(const float4*)&ws[k][8 * ty];
            float4 w1 = *(const float4*)&ws[k][8 * ty + 4];
            float wa[8] = {w0.x, w0.y, w0.z, w0.w, w1.x, w1.y, w1.z, w1.w};
#pragma unroll
            for (int i = 0; i < 8; i++) {
                u64 a2 = pack2(wa[i], wa[i]);
#pragma unroll
                for (int j = 0; j < 4; j++) ffma2(acc2[i][j], a2, bp[j]);
            }
        }
        __syncthreads();
    }

    if (z == 2) {
#pragma unroll
        for (int i = 0; i < 8; i++) {
            int   o  = 8 * ty + i;
            float bv = bi[o];
#pragma unroll
            for (int j = 0; j < 4; j++) {
                float2 f = unpack2(acc2[i][j]);
                int    n = n0 + 8 * tx + 2 * j;
                __half2 hv = __floats2half2_rn(f.x + bv, f.y + bv);
                *(__half2*)&g_vt[((size_t)b * CI + o) * NP + n] = hv;
            }
        }
    } else {
        __half* dh = (z == 0) ? g_qh : g_kh;
        __half* dc = (z == 0) ? g_qc : g_kc;
        const float sc = (z == 0) ? LOG2E : 1.0f;
#pragma unroll
        for (int jj = 0; jj < 8; jj++) {
            int n = n0 + 8 * tx + jj;
            __half hs[8], cs[8];
#pragma unroll
            for (int i = 0; i < 8; i++) {
                float2 f = unpack2(acc2[i][jj >> 1]);
                float  v = (((jj & 1) ? f.y : f.x) + bi[8 * ty + i]) * sc;
                __half h = __float2half_rn(v);
                float  hf = __half2float(h);
                float  l  = v - hf;
                hs[i] = h;
                // theta: qc = qh/64 + ql ; phi: kc = kh + 64*kl
                cs[i] = (z == 0) ? __float2half_rn(hf * 0.015625f + l)
                                 : __float2half_rn(hf + 64.0f * l);
            }
            size_t base = ((size_t)b * NP + n) * CI + 8 * ty;
            *(uint4*)&dh[base] = *(uint4*)hs;
            *(uint4*)&dc[base] = *(uint4*)cs;
        }
    }
}

// =================================================================
// Kernel 2: flash attention, 32 q-rows/warp, 2-pass QK^T, KV-split 2.
// CTA: 256 q-rows (8 warps x 32), kv range 2048 in 32 tiles of 64.
// s_final = (63/64)*(qh.kh) + (qh/64+ql).(kh+64kl)
// Single-buffered K/V with phase-shifted cp.async prefetch.
// =================================================================
#define QSTR 304   // 152 halves: 76 words == 12 mod 32 -> conflict-free ldmatrix
#define KSTR 304
#define VSTR 144   // 36 words == 4 mod 32
#define OFF_QH 0
#define OFF_QC 77824
#define OFF_KH 155648
#define OFF_KC 175104
#define OFF_V  194560
#define SMEM_ATTN 212992
#define KV_TILES 32

__device__ __forceinline__ void load_k(u32 s32, int m0,
                                       const __half* gkh, const __half* gkc, int t)
{
#pragma unroll
    for (int i = 0; i < 4; i++) {
        int id = i * 256 + t;
        int row = id >> 4, c = id & 15;
        cpa(s32 + OFF_KH + row * KSTR + c * 16, gkh + (size_t)(m0 + row) * CI + c * 8);
        cpa(s32 + OFF_KC + row * KSTR + c * 16, gkc + (size_t)(m0 + row) * CI + c * 8);
    }
}
__device__ __forceinline__ void load_v(u32 s32, int m0, const __half* gvt, int t)
{
#pragma unroll
    for (int i = 0; i < 4; i++) {
        int id = i * 256 + t;
        int row = id >> 3, c = id & 7;
        cpa(s32 + OFF_V + row * VSTR + c * 16, gvt + (size_t)row * NP + m0 + c * 8);
    }
}

__global__ __launch_bounds__(256, 1) void attn_kernel()
{
    extern __shared__ __align__(128) char smem[];
    const u32 s32   = smem_u32(smem);
    const int t     = threadIdx.x;
    const int lane  = t & 31;
    const int wr    = (t >> 5) * 32;          // warp's q-row base (32 rows/warp)
    const int row0  = blockIdx.x * 256;
    const int split = blockIdx.y;
    const int b     = blockIdx.z;
    const int kv0   = split * (NP / 2);

    const int lrow = lane & 15;
    const int lcol = (lane >> 4) * 16;
    const int g    = lane >> 2;
    const int c2   = (lane & 3) * 2;

    const __half* gqh = g_qh + ((size_t)b * NP + row0) * CI;
    const __half* gqc = g_qc + ((size_t)b * NP + row0) * CI;
    const __half* gkh = g_kh + ((size_t)b * NP + kv0) * CI;
    const __half* gkc = g_kc + ((size_t)b * NP + kv0) * CI;
    const __half* gvt = g_vt + (size_t)b * CI * NP + kv0;

    // prologue: G0 = {Q(h+c), K(0)}, G1 = {V(0)}
#pragma unroll
    for (int i = 0; i < 16; i++) {
        int id = i * 256 + t;
        int row = id >> 4, c = id & 15;
        cpa(s32 + OFF_QH + row * QSTR + c * 16, gqh + (size_t)row * CI + c * 8);
        cpa(s32 + OFF_QC + row * QSTR + c * 16, gqc + (size_t)row * CI + c * 8);
    }
    load_k(s32, 0, gkh, gkc, t);
    CP_COMMIT();
    load_v(s32, 0, gvt, t);
    CP_COMMIT();

    float o[2][16][4];
#pragma unroll
    for (int mf = 0; mf < 2; mf++)
#pragma unroll
        for (int nf = 0; nf < 16; nf++)
#pragma unroll
            for (int q = 0; q < 4; q++) o[mf][nf][q] = 0.0f;
    float mrun[2][2] = {{-1e30f, -1e30f}, {-1e30f, -1e30f}};
    float lrun[2][2] = {{0.0f, 0.0f}, {0.0f, 0.0f}};

    for (int tile = 0; tile < KV_TILES; tile++) {
        CP_WAIT1();          // K(tile) (and Q) arrived
        __syncthreads();

        float s[2][8][4];
#pragma unroll
        for (int mf = 0; mf < 2; mf++)
#pragma unroll
            for (int nf = 0; nf < 8; nf++)
#pragma unroll
                for (int q = 0; q < 4; q++) s[mf][nf][q] = 0.0f;

        // ---- pass 1: s = qh . kh^T ----
#pragma unroll
        for (int kc = 0; kc < 8; kc++) {
            u32 qa[2][4];
#pragma unroll
            for (int mf = 0; mf < 2; mf++)
                ldm4(qa[mf][0], qa[mf][1], qa[mf][2], qa[mf][3],
                     s32 + OFF_QH + (wr + mf * 16 + lrow) * QSTR + kc * 32 + lcol);
#pragma unroll
            for (int nb = 0; nb < 4; nb++) {
                u32 k0, k1, k2, k3;
                ldm4(k0, k1, k2, k3,
                     s32 + OFF_KH + (nb * 16 + lrow) * KSTR + kc * 32 + lcol);
#pragma unroll
                for (int mf = 0; mf < 2; mf++) {
                    mma16816(s[mf][2 * nb],     qa[mf][0], qa[mf][1], qa[mf][2], qa[mf][3], k0, k2);
                    mma16816(s[mf][2 * nb + 1], qa[mf][0], qa[mf][1], qa[mf][2], qa[mf][3], k1, k3);
                }
            }
        }
        // ---- scale: s *= 63/64 ----
#pragma unroll
        for (int mf = 0; mf < 2; mf++)
#pragma unroll
            for (int nf = 0; nf < 8; nf++)
#pragma unroll
                for (int q = 0; q < 4; q++) s[mf][nf][q] *= 0.984375f;

        // ---- pass 2: s += qc . kc^T  (equals +qhkh/64 + cross terms) ----
#pragma unroll
        for (int kc = 0; kc < 8; kc++) {
            u32 qa[2][4];
#pragma unroll
            for (int mf = 0; mf < 2; mf++)
                ldm4(qa[mf][0], qa[mf][1], qa[mf][2], qa[mf][3],
                     s32 + OFF_QC + (wr + mf * 16 + lrow) * QSTR + kc * 32 + lcol);
#pragma unroll
            for (int nb = 0; nb < 4; nb++) {
                u32 k0, k1, k2, k3;
                ldm4(k0, k1, k2, k3,
                     s32 + OFF_KC + (nb * 16 + lrow) * KSTR + kc * 32 + lcol);
#pragma unroll
                for (int mf = 0; mf < 2; mf++) {
                    mma16816(s[mf][2 * nb],     qa[mf][0], qa[mf][1], qa[mf][2], qa[mf][3], k0, k2);
                    mma16816(s[mf][2 * nb + 1], qa[mf][0], qa[mf][1], qa[mf][2], qa[mf][3], k1, k3);
                }
            }
        }

        __syncthreads();     // all warps done reading K buffer
        if (tile + 1 < KV_TILES) load_k(s32, (tile + 1) * 64, gkh, gkc, t);
        CP_COMMIT();         // commit even if empty (keeps group bookkeeping)

        // ---- online softmax (rows g, g+8 in each of 2 m-frags) ----
        float corr[2][2];
        u32   p[2][4][4];
#pragma unroll
        for (int mf = 0; mf < 2; mf++) {
            float mx0 = fmaxf(s[mf][0][0], s[mf][0][1]);
            float mx1 = fmaxf(s[mf][0][2], s[mf][0][3]);
#pragma unroll
            for (int nf = 1; nf < 8; nf++) {
                mx0 = fmaxf(mx0, fmaxf(s[mf][nf][0], s[mf][nf][1]));
                mx1 = fmaxf(mx1, fmaxf(s[mf][nf][2], s[mf][nf][3]));
            }
            mx0 = fmaxf(mx0, __shfl_xor_sync(0xffffffffu, mx0, 1));
            mx0 = fmaxf(mx0, __shfl_xor_sync(0xffffffffu, mx0, 2));
            mx1 = fmaxf(mx1, __shfl_xor_sync(0xffffffffu, mx1, 1));
            mx1 = fmaxf(mx1, __shfl_xor_sync(0xffffffffu, mx1, 2));
            float mnew0 = fmaxf(mrun[mf][0], mx0);
            float mnew1 = fmaxf(mrun[mf][1], mx1);
            corr[mf][0] = ex2(mrun[mf][0] - mnew0);
            corr[mf][1] = ex2(mrun[mf][1] - mnew1);
            mrun[mf][0] = mnew0;
            mrun[mf][1] = mnew1;

            float ls0 = 0.0f, ls1 = 0.0f;
#pragma unroll
            for (int kc2 = 0; kc2 < 4; kc2++) {
#pragma unroll
                for (int half = 0; half < 2; half++) {
                    int nf = 2 * kc2 + half;
                    float e0 = ex2(s[mf][nf][0] - mnew0);
                    float e1 = ex2(s[mf][nf][1] - mnew0);
                    float e2 = ex2(s[mf][nf][2] - mnew1);
                    float e3 = ex2(s[mf][nf][3] - mnew1);
                    ls0 += e0 + e1;
                    ls1 += e2 + e3;
                    __half2 h01 = __floats2half2_rn(e0, e1);
                    __half2 h23 = __floats2half2_rn(e2, e3);
                    p[mf][kc2][2 * half]     = *(u32*)&h01;
                    p[mf][kc2][2 * half + 1] = *(u32*)&h23;
                }
            }
            ls0 += __shfl_xor_sync(0xffffffffu, ls0, 1);
            ls0 += __shfl_xor_sync(0xffffffffu, ls0, 2);
            ls1 += __shfl_xor_sync(0xffffffffu, ls1, 1);
            ls1 += __shfl_xor_sync(0xffffffffu, ls1, 2);
            lrun[mf][0] = lrun[mf][0] * corr[mf][0] + ls0;
            lrun[mf][1] = lrun[mf][1] * corr[mf][1] + ls1;
        }

        if (__any_sync(0xffffffffu,
                       fminf(fminf(corr[0][0], corr[0][1]),
                             fminf(corr[1][0], corr[1][1])) < 0.99999f)) {
#pragma unroll
            for (int mf = 0; mf < 2; mf++)
#pragma unroll
                for (int nf = 0; nf < 16; nf++) {
                    o[mf][nf][0] *= corr[mf][0]; o[mf][nf][1] *= corr[mf][0];
                    o[mf][nf][2] *= corr[mf][1]; o[mf][nf][3] *= corr[mf][1];
                }
        }

        CP_WAIT1();          // V(tile) arrived
        __syncthreads();

        // ---- O += P . V ----
#pragma unroll
        for (int kc2 = 0; kc2 < 4; kc2++) {
#pragma unroll
            for (int dg = 0; dg < 8; dg++) {
                u32 v0, v1, v2, v3;
                ldm4(v0, v1, v2, v3,
                     s32 + OFF_V + (dg * 16 + lrow) * VSTR + kc2 * 32 + lcol);
#pragma unroll
                for (int mf = 0; mf < 2; mf++) {
                    mma16816(o[mf][2 * dg],
                             p[mf][kc2][0], p[mf][kc2][1], p[mf][kc2][2], p[mf][kc2][3], v0, v2);
                    mma16816(o[mf][2 * dg + 1],
                             p[mf][kc2][0], p[mf][kc2][1], p[mf][kc2][2], p[mf][kc2][3], v1, v3);
                }
            }
        }

        __syncthreads();     // all warps done reading V buffer
        if (tile + 1 < KV_TILES) load_v(s32, (tile + 1) * 64, gvt, t);
        CP_COMMIT();
    }

    // ---- store unnormalized partials + (m, l) ----
    float* po = g_po + ((size_t)(split * BB + b) * NP + row0 + wr) * CI;
    float* pm = g_pm + (size_t)(split * BB + b) * NP + row0 + wr;
    float* pl = g_pl + (size_t)(split * BB + b) * NP + row0 + wr;
#pragma unroll
    for (int mf = 0; mf < 2; mf++) {
        int r0 = mf * 16 + g;
#pragma unroll
        for (int nf = 0; nf < 16; nf++) {
            *(float2*)&po[(size_t)r0 * CI + nf * 8 + c2] =
                make_float2(o[mf][nf][0], o[mf][nf][1]);
            *(float2*)&po[(size_t)(r0 + 8) * CI + nf * 8 + c2] =
                make_float2(o[mf][nf][2], o[mf][nf][3]);
        }
        if ((lane & 3) == 0) {
            pm[r0] = mrun[mf][0]; pm[r0 + 8] = mrun[mf][1];
            pl[r0] = lrun[mf][0]; pl[r0 + 8] = lrun[mf][1];
        }
    }
}

// =================================================================
// Kernel 2b: merge the two kv-split partials into g_o.
// =================================================================
__global__ __launch_bounds__(256) void merge_kernel()
{
    const int t   = threadIdx.x;
    const int bn  = blockIdx.x * 64 + (t >> 2);   // 0 .. BB*NP-1
    const int qd  = (t & 3) * 32;                 // d quarter

    float m0 = g_pm[bn], m1 = g_pm[BB * NP + bn];
    float l0 = g_pl[bn], l1 = g_pl[BB * NP + bn];
    float m  = fmaxf(m0, m1);
    float w0 = ex2(m0 - m), w1 = ex2(m1 - m);
    float inv = 1.0f / (w0 * l0 + w1 * l1);
    w0 *= inv; w1 *= inv;

    const float* p0 = g_po + (size_t)bn * CI + qd;
    const float* p1 = g_po + (size_t)(BB * NP + bn) * CI + qd;
    float* dst = g_o + (size_t)bn * CI + qd;
#pragma unroll
    for (int i = 0; i < 8; i++) {
        float4 a = *(const float4*)&p0[4 * i];
        float4 c = *(const float4*)&p1[4 * i];
        float4 r = make_float4(a.x * w0 + c.x * w1, a.y * w0 + c.y * w1,
                               a.z * w0 + c.z * w1, a.w * w0 + c.w * w1);
        *(float4*)&dst[4 * i] = r;
    }
}

// =================================================================
// Kernel 3: output projection + bias + residual.
// =================================================================
__global__ __launch_bounds__(256) void outproj_kernel(
    const float* __restrict__ x,
    const float* __restrict__ ww, const float* __restrict__ wb,
    float* __restrict__ out)
{
    __shared__ float os[16][132];
    __shared__ float ws[16][68];

    const int b  = blockIdx.z;
    const int c0 = blockIdx.y * 64;
    const int n0 = blockIdx.x * 128;
    const int t  = threadIdx.x, tx = t & 15, ty = t >> 4;

    u64 acc2[4][4];
#pragma unroll
    for (int i = 0; i < 4; i++)
#pragma unroll
        for (int j = 0; j < 4; j++) acc2[i][j] = 0ull;

    const float* ob = g_o + (size_t)b * NP * CI;

    for (int o0 = 0; o0 < CI; o0 += 16) {
        {
            int k4 = (t & 3) * 4;
            int nn = t >> 2;
#pragma unroll
            for (int hh = 0; hh < 2; hh++) {
                float4 v = *(const float4*)&ob[(size_t)(n0 + nn + 64 * hh) * CI + o0 + k4];
                os[k4 + 0][nn + 64 * hh] = v.x;
                os[k4 + 1][nn + 64 * hh] = v.y;
                os[k4 + 2][nn + 64 * hh] = v.z;
                os[k4 + 3][nn + 64 * hh] = v.w;
            }
        }
        {
            int k = t & 15, cc = t >> 4;
#pragma unroll
            for (int p = 0; p < 4; p++)
                ws[k][cc + 16 * p] = ww[(size_t)(c0 + cc + 16 * p) * CI + o0 + k];
        }
        __syncthreads();
#pragma unroll
        for (int k = 0; k < 16; k++) {
            float4 b0 = *(const float4*)&os[k][8 * tx];
            float4 b1 = *(const float4*)&os[k][8 * tx + 4];
            u64 bp[4];
            bp[0] = pack2(b0.x, b0.y); bp[1] = pack2(b0.z, b0.w);
            bp[2] = pack2(b1.x, b1.y); bp[3] = pack2(b1.z, b1.w);
            float4 wv = *(const float4*)&ws[k][4 * ty];
            float wa[4] = {wv.x, wv.y, wv.z, wv.w};
#pragma unroll
            for (int i = 0; i < 4; i++) {
                u64 a2 = pack2(wa[i], wa[i]);
#pragma unroll
                for (int j = 0; j < 4; j++) ffma2(acc2[i][j], a2, bp[j]);
            }
        }
        __syncthreads();
    }

#pragma unroll
    for (int i = 0; i < 4; i++) {
        int    c    = c0 + 4 * ty + i;
        float  bv   = wb[c];
        size_t base = ((size_t)b * CC + c) * NP + n0 + 8 * tx;
        float4 xv0  = *(const float4*)&x[base];
        float4 xv1  = *(const float4*)&x[base + 4];
        float2 f0 = unpack2(acc2[i][0]);
        float2 f1 = unpack2(acc2[i][1]);
        float2 f2 = unpack2(acc2[i][2]);
        float2 f3 = unpack2(acc2[i][3]);
        float4 r0 = make_float4(f0.x + bv + xv0.x, f0.y + bv + xv0.y,
                                f1.x + bv + xv0.z, f1.y + bv + xv0.w);
        float4 r1 = make_float4(f2.x + bv + xv1.x, f2.y + bv + xv1.y,
                                f3.x + bv + xv1.z, f3.y + bv + xv1.w);
        *(float4*)&out[base]     = r0;
        *(float4*)&out[base + 4] = r1;
    }
}

// =================================================================
extern "C" void kernel_launch(void* const* d_in, const int* in_sizes, int n_in,
                              void* d_out, int out_size)
{
    const float* x  = (const float*)d_in[0];
    const float* tw = (const float*)d_in[1];
    const float* tb = (const float*)d_in[2];
    const float* pw = (const float*)d_in[3];
    const float* pb = (const float*)d_in[4];
    const float* gw = (const float*)d_in[5];
    const float* gb = (const float*)d_in[6];
    const float* ww = (const float*)d_in[7];
    const float* wb = (const float*)d_in[8];
    float* out = (float*)d_out;

    cudaFuncSetAttribute(attn_kernel, cudaFuncAttributeMaxDynamicSharedMemorySize, SMEM_ATTN);

    proj_kernel<<<dim3(NP / 128, BB, 3), 256>>>(x, tw, tb, pw, pb, gw, gb);
    attn_kernel<<<dim3(NP / 256, 2, BB), 256, SMEM_ATTN>>>();
    merge_kernel<<<BB * NP / 64, 256>>>();
    outproj_kernel<<<dim3(NP / 128, CC / 64, BB), 256>>>(x, ww, wb, out);
}

// round 6
// speedup vs baseline: 4.3822x; 1.0671x over previous
#include <cuda_runtime.h>
#include <cuda_fp16.h>
#include <math.h>
#include <stdint.h>

#define BB 4
#define CC 256
#define CI 128
#define NP 4096
#define LOG2E 1.4426950408889634f

typedef unsigned long long u64;
typedef unsigned int u32;

// Scratch (device globals: allocation-free rule)
__device__ __half g_qh[BB * NP * CI];  // theta(x)*log2e hi         : (b, n, o)
__device__ __half g_qc[BB * NP * CI];  // qh/64 + ql (correction)   : (b, n, o)
__device__ __half g_kh[BB * NP * CI];  // phi(x) hi                 : (b, m, o)
__device__ __half g_kc[BB * NP * CI];  // kh + 64*kl (correction)   : (b, m, o)
__device__ __half g_vt[BB * CI * NP];  // g(x) transposed           : (b, o, m)
__device__ float  g_po[2 * BB * NP * CI];  // unnormalized partial O per kv-split
__device__ float  g_pm[2 * BB * NP];       // partial running max (log2 domain)
__device__ float  g_pl[2 * BB * NP];       // partial running sum

// ---------------- packed fp32x2 helpers ----------------
__device__ __forceinline__ u64 pack2(float lo, float hi) {
    u64 r;
    asm("mov.b64 %0, {%1, %2};" : "=l"(r) : "f"(lo), "f"(hi));
    return r;
}
__device__ __forceinline__ float2 unpack2(u64 v) {
    float2 f;
    asm("mov.b64 {%0, %1}, %2;" : "=f"(f.x), "=f"(f.y) : "l"(v));
    return f;
}
__device__ __forceinline__ void ffma2(u64& d, u64 a, u64 b) {
    asm("fma.rn.f32x2 %0, %1, %2, %0;" : "+l"(d) : "l"(a), "l"(b));
}
__device__ __forceinline__ float ex2(float x) {
    float y;
    asm("ex2.approx.ftz.f32 %0, %1;" : "=f"(y) : "f"(x));
    return y;
}
__device__ __forceinline__ u32 smem_u32(const void* p) {
    u32 a;
    asm("{ .reg .u64 t; cvta.to.shared.u64 t, %1; cvt.u32.u64 %0, t; }" : "=r"(a) : "l"(p));
    return a;
}

// ---------------- mma.sync / ldmatrix / cp.async ----------------
__device__ __forceinline__ void ldm4(u32& r0, u32& r1, u32& r2, u32& r3, u32 addr) {
    asm volatile("ldmatrix.sync.aligned.m8n8.x4.shared.b16 {%0,%1,%2,%3}, [%4];"
                 : "=r"(r0), "=r"(r1), "=r"(r2), "=r"(r3) : "r"(addr));
}
__device__ __forceinline__ void mma16816(float* c, u32 a0, u32 a1, u32 a2, u32 a3,
                                         u32 b0, u32 b1) {
    asm volatile(
        "mma.sync.aligned.m16n8k16.row.col.f32.f16.f16.f32 "
        "{%0,%1,%2,%3}, {%4,%5,%6,%7}, {%8,%9}, {%0,%1,%2,%3};"
        : "+f"(c[0]), "+f"(c[1]), "+f"(c[2]), "+f"(c[3])
        : "r"(a0), "r"(a1), "r"(a2), "r"(a3), "r"(b0), "r"(b1));
}
__device__ __forceinline__ void cpa(u32 s, const void* g) {
    asm volatile("cp.async.cg.shared.global [%0], [%1], 16;" :: "r"(s), "l"(g));
}
#define CP_COMMIT() asm volatile("cp.async.commit_group;")
#define CP_WAIT1()  asm volatile("cp.async.wait_group 1;")

// =================================================================
// Kernel 1: QKV projections (fp32 FFMA compute).
// =================================================================
__global__ __launch_bounds__(256, 2) void proj_kernel(
    const float* __restrict__ x,
    const float* __restrict__ tw, const float* __restrict__ tb,
    const float* __restrict__ pw, const float* __restrict__ pb,
    const float* __restrict__ gw, const float* __restrict__ gb)
{
    __shared__ float xs[16][132];
    __shared__ float ws[16][132];

    const int z  = blockIdx.z;
    const int b  = blockIdx.y;
    const int n0 = blockIdx.x * 128;
    const float* W  = (z == 0) ? tw : (z == 1) ? pw : gw;
    const float* bi = (z == 0) ? tb : (z == 1) ? pb : gb;

    const int t  = threadIdx.x;
    const int tx = t & 15, ty = t >> 4;

    u64 acc2[8][4];
#pragma unroll
    for (int i = 0; i < 8; i++)
#pragma unroll
        for (int j = 0; j < 4; j++) acc2[i][j] = 0ull;

    const float* xb = x + (size_t)b * CC * NP + n0;

    for (int c0 = 0; c0 < CC; c0 += 16) {
        {
            int k   = t >> 5;
            int nn4 = (t & 31) * 4;
            *(float4*)&xs[k][nn4]     = *(const float4*)&xb[(size_t)(c0 + k) * NP + nn4];
            *(float4*)&xs[k + 8][nn4] = *(const float4*)&xb[(size_t)(c0 + k + 8) * NP + nn4];
        }
        {
            int k = t & 15, oo = t >> 4;
#pragma unroll
            for (int p = 0; p < 8; p++)
                ws[k][oo + 16 * p] = W[(size_t)(oo + 16 * p) * CC + c0 + k];
        }
        __syncthreads();
#pragma unroll
        for (int k = 0; k < 16; k++) {
            float4 b0 = *(const float4*)&xs[k][8 * tx];
            float4 b1 = *(const float4*)&xs[k][8 * tx + 4];
            u64 bp[4];
            bp[0] = pack2(b0.x, b0.y); bp[1] = pack2(b0.z, b0.w);
            bp[2] = pack2(b1.x, b1.y); bp[3] = pack2(b1.z, b1.w);
            float4 w0 = *(const float4*)&ws[k][8 * ty];
            float4 w1 = *(const float4*)&ws[k][8 * ty + 4];
            float wa[8] = {w0.x, w0.y, w0.z, w0.w, w1.x, w1.y, w1.z, w1.w};
#pragma unroll
            for (int i = 0; i < 8; i++) {
                u64 a2 = pack2(wa[i], wa[i]);
#pragma unroll
                for (int j = 0; j < 4; j++) ffma2(acc2[i][j], a2, bp[j]);
            }
        }
        __syncthreads();
    }

    if (z == 2) {
#pragma unroll
        for (int i = 0; i < 8; i++) {
            int   o  = 8 * ty + i;
            float bv = bi[o];
#pragma unroll
            for (int j = 0; j < 4; j++) {
                float2 f = unpack2(acc2[i][j]);
                int    n = n0 + 8 * tx + 2 * j;
                __half2 hv = __floats2half2_rn(f.x + bv, f.y + bv);
                *(__half2*)&g_vt[((size_t)b * CI + o) * NP + n] = hv;
            }
        }
    } else {
        __half* dh = (z == 0) ? g_qh : g_kh;
        __half* dc = (z == 0) ? g_qc : g_kc;
        const float sc = (z == 0) ? LOG2E : 1.0f;
#pragma unroll
        for (int jj = 0; jj < 8; jj++) {
            int n = n0 + 8 * tx + jj;
            __half hs[8], cs[8];
#pragma unroll
            for (int i = 0; i < 8; i++) {
                float2 f = unpack2(acc2[i][jj >> 1]);
                float  v = (((jj & 1) ? f.y : f.x) + bi[8 * ty + i]) * sc;
                __half h = __float2half_rn(v);
                float  hf = __half2float(h);
                float  l  = v - hf;
                hs[i] = h;
                cs[i] = (z == 0) ? __float2half_rn(hf * 0.015625f + l)
                                 : __float2half_rn(hf + 64.0f * l);
            }
            size_t base = ((size_t)b * NP + n) * CI + 8 * ty;
            *(uint4*)&dh[base] = *(uint4*)hs;
            *(uint4*)&dc[base] = *(uint4*)cs;
        }
    }
}

// =================================================================
// Kernel 2: flash attention, 128 threads/CTA (4 warps x 32 q-rows),
// 2-pass QK^T, KV-split 2, swizzled smem, 2 CTAs/SM.
// s_final = (63/64)*(qh.kh) + (qh/64+ql).(kh+64kl)
// =================================================================
#define SWZ256(x) ((x) ^ (((x) >> 4) & 0x70))   // 256B rows (Q, K)
#define SWZ128(x) ((x) ^ (((x) >> 3) & 0x70))   // 128B rows (V)
#define OFF_QH 0
#define OFF_QC 32768
#define OFF_KH 65536
#define OFF_KC 81920
#define OFF_V  98304
#define SMEM_ATTN 114688
#define KV_TILES 32

__device__ __forceinline__ void load_k(u32 s32, int m0,
                                       const __half* gkh, const __half* gkc, int t)
{
#pragma unroll
    for (int i = 0; i < 8; i++) {
        int id = i * 128 + t;
        int row = id >> 4, c = id & 15;
        u32 sw = SWZ256(row * 256 + c * 16);
        cpa(s32 + OFF_KH + sw, gkh + (size_t)(m0 + row) * CI + c * 8);
        cpa(s32 + OFF_KC + sw, gkc + (size_t)(m0 + row) * CI + c * 8);
    }
}
__device__ __forceinline__ void load_v(u32 s32, int m0, const __half* gvt, int t)
{
#pragma unroll
    for (int i = 0; i < 8; i++) {
        int id = i * 128 + t;
        int row = id >> 3, c = id & 7;
        cpa(s32 + OFF_V + SWZ128(row * 128 + c * 16), gvt + (size_t)row * NP + m0 + c * 8);
    }
}

__global__ __launch_bounds__(128, 2) void attn_kernel()
{
    extern __shared__ __align__(128) char smem[];
    const u32 s32   = smem_u32(smem);
    const int t     = threadIdx.x;
    const int lane  = t & 31;
    const int wr    = (t >> 5) * 32;          // warp's q-row base (32 rows/warp)
    const int row0  = blockIdx.x * 128;
    const int split = blockIdx.y;
    const int b     = blockIdx.z;
    const int kv0   = split * (NP / 2);

    const int lrow = lane & 15;
    const int lcol = (lane >> 4) * 16;
    const int g    = lane >> 2;
    const int c2   = (lane & 3) * 2;

    const __half* gqh = g_qh + ((size_t)b * NP + row0) * CI;
    const __half* gqc = g_qc + ((size_t)b * NP + row0) * CI;
    const __half* gkh = g_kh + ((size_t)b * NP + kv0) * CI;
    const __half* gkc = g_kc + ((size_t)b * NP + kv0) * CI;
    const __half* gvt = g_vt + (size_t)b * CI * NP + kv0;

    // prologue: G0 = {Q(h+c), K(0)}, G1 = {V(0)}
#pragma unroll
    for (int i = 0; i < 16; i++) {
        int id = i * 128 + t;
        int row = id >> 4, c = id & 15;
        u32 sw = SWZ256(row * 256 + c * 16);
        cpa(s32 + OFF_QH + sw, gqh + (size_t)row * CI + c * 8);
        cpa(s32 + OFF_QC + sw, gqc + (size_t)row * CI + c * 8);
    }
    load_k(s32, 0, gkh, gkc, t);
    CP_COMMIT();
    load_v(s32, 0, gvt, t);
    CP_COMMIT();

    float o[2][16][4];
#pragma unroll
    for (int mf = 0; mf < 2; mf++)
#pragma unroll
        for (int nf = 0; nf < 16; nf++)
#pragma unroll
            for (int q = 0; q < 4; q++) o[mf][nf][q] = 0.0f;
    float mrun[2][2] = {{-1e30f, -1e30f}, {-1e30f, -1e30f}};
    float lrun[2][2] = {{0.0f, 0.0f}, {0.0f, 0.0f}};

    for (int tile = 0; tile < KV_TILES; tile++) {
        CP_WAIT1();          // K(tile) (and Q) arrived
        __syncthreads();

        float s[2][8][4];
#pragma unroll
        for (int mf = 0; mf < 2; mf++)
#pragma unroll
            for (int nf = 0; nf < 8; nf++)
#pragma unroll
                for (int q = 0; q < 4; q++) s[mf][nf][q] = 0.0f;

        // ---- pass 1: s = qh . kh^T ----
#pragma unroll
        for (int kc = 0; kc < 8; kc++) {
            u32 qa[2][4];
#pragma unroll
            for (int mf = 0; mf < 2; mf++)
                ldm4(qa[mf][0], qa[mf][1], qa[mf][2], qa[mf][3],
                     s32 + OFF_QH + SWZ256((wr + mf * 16 + lrow) * 256 + kc * 32 + lcol));
#pragma unroll
            for (int nb = 0; nb < 4; nb++) {
                u32 k0, k1, k2, k3;
                ldm4(k0, k1, k2, k3,
                     s32 + OFF_KH + SWZ256((nb * 16 + lrow) * 256 + kc * 32 + lcol));
#pragma unroll
                for (int mf = 0; mf < 2; mf++) {
                    mma16816(s[mf][2 * nb],     qa[mf][0], qa[mf][1], qa[mf][2], qa[mf][3], k0, k2);
                    mma16816(s[mf][2 * nb + 1], qa[mf][0], qa[mf][1], qa[mf][2], qa[mf][3], k1, k3);
                }
            }
        }
        // ---- scale: s *= 63/64 ----
#pragma unroll
        for (int mf = 0; mf < 2; mf++)
#pragma unroll
            for (int nf = 0; nf < 8; nf++)
#pragma unroll
                for (int q = 0; q < 4; q++) s[mf][nf][q] *= 0.984375f;

        // ---- pass 2: s += qc . kc^T ----
#pragma unroll
        for (int kc = 0; kc < 8; kc++) {
            u32 qa[2][4];
#pragma unroll
            for (int mf = 0; mf < 2; mf++)
                ldm4(qa[mf][0], qa[mf][1], qa[mf][2], qa[mf][3],
                     s32 + OFF_QC + SWZ256((wr + mf * 16 + lrow) * 256 + kc * 32 + lcol));
#pragma unroll
            for (int nb = 0; nb < 4; nb++) {
                u32 k0, k1, k2, k3;
                ldm4(k0, k1, k2, k3,
                     s32 + OFF_KC + SWZ256((nb * 16 + lrow) * 256 + kc * 32 + lcol));
#pragma unroll
                for (int mf = 0; mf < 2; mf++) {
                    mma16816(s[mf][2 * nb],     qa[mf][0], qa[mf][1], qa[mf][2], qa[mf][3], k0, k2);
                    mma16816(s[mf][2 * nb + 1], qa[mf][0], qa[mf][1], qa[mf][2], qa[mf][3], k1, k3);
                }
            }
        }

        __syncthreads();     // all warps done reading K buffer
        if (tile + 1 < KV_TILES) load_k(s32, (tile + 1) * 64, gkh, gkc, t);
        CP_COMMIT();

        // ---- online softmax ----
        float corr[2][2];
        u32   p[2][4][4];
#pragma unroll
        for (int mf = 0; mf < 2; mf++) {
            float mx0 = fmaxf(s[mf][0][0], s[mf][0][1]);
            float mx1 = fmaxf(s[mf][0][2], s[mf][0][3]);
#pragma unroll
            for (int nf = 1; nf < 8; nf++) {
                mx0 = fmaxf(mx0, fmaxf(s[mf][nf][0], s[mf][nf][1]));
                mx1 = fmaxf(mx1, fmaxf(s[mf][nf][2], s[mf][nf][3]));
            }
            mx0 = fmaxf(mx0, __shfl_xor_sync(0xffffffffu, mx0, 1));
            mx0 = fmaxf(mx0, __shfl_xor_sync(0xffffffffu, mx0, 2));
            mx1 = fmaxf(mx1, __shfl_xor_sync(0xffffffffu, mx1, 1));
            mx1 = fmaxf(mx1, __shfl_xor_sync(0xffffffffu, mx1, 2));
            float mnew0 = fmaxf(mrun[mf][0], mx0);
            float mnew1 = fmaxf(mrun[mf][1], mx1);
            corr[mf][0] = ex2(mrun[mf][0] - mnew0);
            corr[mf][1] = ex2(mrun[mf][1] - mnew1);
            mrun[mf][0] = mnew0;
            mrun[mf][1] = mnew1;

            float ls0 = 0.0f, ls1 = 0.0f;
#pragma unroll
            for (int kc2 = 0; kc2 < 4; kc2++) {
#pragma unroll
                for (int half = 0; half < 2; half++) {
                    int nf = 2 * kc2 + half;
                    float e0 = ex2(s[mf][nf][0] - mnew0);
                    float e1 = ex2(s[mf][nf][1] - mnew0);
                    float e2 = ex2(s[mf][nf][2] - mnew1);
                    float e3 = ex2(s[mf][nf][3] - mnew1);
                    ls0 += e0 + e1;
                    ls1 += e2 + e3;
                    __half2 h01 = __floats2half2_rn(e0, e1);
                    __half2 h23 = __floats2half2_rn(e2, e3);
                    p[mf][kc2][2 * half]     = *(u32*)&h01;
                    p[mf][kc2][2 * half + 1] = *(u32*)&h23;
                }
            }
            ls0 += __shfl_xor_sync(0xffffffffu, ls0, 1);
            ls0 += __shfl_xor_sync(0xffffffffu, ls0, 2);
            ls1 += __shfl_xor_sync(0xffffffffu, ls1, 1);
            ls1 += __shfl_xor_sync(0xffffffffu, ls1, 2);
            lrun[mf][0] = lrun[mf][0] * corr[mf][0] + ls0;
            lrun[mf][1] = lrun[mf][1] * corr[mf][1] + ls1;
        }

        if (__any_sync(0xffffffffu,
                       fminf(fminf(corr[0][0], corr[0][1]),
                             fminf(corr[1][0], corr[1][1])) < 0.99999f)) {
#pragma unroll
            for (int mf = 0; mf < 2; mf++)
#pragma unroll
                for (int nf = 0; nf < 16; nf++) {
                    o[mf][nf][0] *= corr[mf][0]; o[mf][nf][1] *= corr[mf][0];
                    o[mf][nf][2] *= corr[mf][1]; o[mf][nf][3] *= corr[mf][1];
                }
        }

        CP_WAIT1();          // V(tile) arrived
        __syncthreads();

        // ---- O += P . V ----
#pragma unroll
        for (int kc2 = 0; kc2 < 4; kc2++) {
#pragma unroll
            for (int dg = 0; dg < 8; dg++) {
                u32 v0, v1, v2, v3;
                ldm4(v0, v1, v2, v3,
                     s32 + OFF_V + SWZ128((dg * 16 + lrow) * 128 + kc2 * 32 + lcol));
#pragma unroll
                for (int mf = 0; mf < 2; mf++) {
                    mma16816(o[mf][2 * dg],
                             p[mf][kc2][0], p[mf][kc2][1], p[mf][kc2][2], p[mf][kc2][3], v0, v2);
                    mma16816(o[mf][2 * dg + 1],
                             p[mf][kc2][0], p[mf][kc2][1], p[mf][kc2][2], p[mf][kc2][3], v1, v3);
                }
            }
        }

        __syncthreads();     // all warps done reading V buffer
        if (tile + 1 < KV_TILES) load_v(s32, (tile + 1) * 64, gvt, t);
        CP_COMMIT();
    }

    // ---- store unnormalized partials + (m, l) ----
    float* po = g_po + ((size_t)(split * BB + b) * NP + row0 + wr) * CI;
    float* pm = g_pm + (size_t)(split * BB + b) * NP + row0 + wr;
    float* pl = g_pl + (size_t)(split * BB + b) * NP + row0 + wr;
#pragma unroll
    for (int mf = 0; mf < 2; mf++) {
        int r0 = mf * 16 + g;
#pragma unroll
        for (int nf = 0; nf < 16; nf++) {
            *(float2*)&po[(size_t)r0 * CI + nf * 8 + c2] =
                make_float2(o[mf][nf][0], o[mf][nf][1]);
            *(float2*)&po[(size_t)(r0 + 8) * CI + nf * 8 + c2] =
                make_float2(o[mf][nf][2], o[mf][nf][3]);
        }
        if ((lane & 3) == 0) {
            pm[r0] = mrun[mf][0]; pm[r0 + 8] = mrun[mf][1];
            pl[r0] = lrun[mf][0]; pl[r0 + 8] = lrun[mf][1];
        }
    }
}

// =================================================================
// Kernel 3: fused merge + output projection + bias + residual.
// Tile 128c x 128n, micro 8x8. Merge weights staged per-n in smem.
// =================================================================
__global__ __launch_bounds__(256, 2) void outproj_kernel(
    const float* __restrict__ x,
    const float* __restrict__ ww, const float* __restrict__ wb,
    float* __restrict__ out)
{
    __shared__ float os[16][132];   // [o-chunk][n] merged attention out
    __shared__ float ws[16][132];   // [o-chunk][c]
    __shared__ float wgt[2][128];   // per-n merge weights (incl. 1/l)

    const int b  = blockIdx.z;
    const int c0 = blockIdx.y * 128;
    const int n0 = blockIdx.x * 128;
    const int t  = threadIdx.x, tx = t & 15, ty = t >> 4;

    if (t < 128) {
        int bn = b * NP + n0 + t;
        float m0 = g_pm[bn], m1 = g_pm[BB * NP + bn];
        float l0 = g_pl[bn], l1 = g_pl[BB * NP + bn];
        float m  = fmaxf(m0, m1);
        float w0 = ex2(m0 - m), w1 = ex2(m1 - m);
        float inv = 1.0f / (w0 * l0 + w1 * l1);
        wgt[0][t] = w0 * inv;
        wgt[1][t] = w1 * inv;
    }
    __syncthreads();

    u64 acc2[8][4];
#pragma unroll
    for (int i = 0; i < 8; i++)
#pragma unroll
        for (int j = 0; j < 4; j++) acc2[i][j] = 0ull;

    const float* p0 = g_po + ((size_t)b * NP + n0) * CI;
    const float* p1 = g_po + ((size_t)(BB + b) * NP + n0) * CI;

    for (int o0 = 0; o0 < CI; o0 += 16) {
        {   // merged os[k][nn]: transpose from pixel-major partials
            int k4 = (t & 3) * 4;
            int nn = t >> 2;
#pragma unroll
            for (int hh = 0; hh < 2; hh++) {
                int    n  = nn + 64 * hh;
                float  w0 = wgt[0][n], w1 = wgt[1][n];
                float4 a  = *(const float4*)&p0[(size_t)n * CI + o0 + k4];
                float4 c  = *(const float4*)&p1[(size_t)n * CI + o0 + k4];
                os[k4 + 0][n] = a.x * w0 + c.x * w1;
                os[k4 + 1][n] = a.y * w0 + c.y * w1;
                os[k4 + 2][n] = a.z * w0 + c.z * w1;
                os[k4 + 3][n] = a.w * w0 + c.w * w1;
            }
        }
        {   // ws[k][cc] from w_w (C, CI) row-major
            int k = t & 15, cc = t >> 4;
#pragma unroll
            for (int p = 0; p < 8; p++)
                ws[k][cc + 16 * p] = ww[(size_t)(c0 + cc + 16 * p) * CI + o0 + k];
        }
        __syncthreads();
#pragma unroll
        for (int k = 0; k < 16; k++) {
            float4 b0 = *(const float4*)&os[k][8 * tx];
            float4 b1 = *(const float4*)&os[k][8 * tx + 4];
            u64 bp[4];
            bp[0] = pack2(b0.x, b0.y); bp[1] = pack2(b0.z, b0.w);
            bp[2] = pack2(b1.x, b1.y); bp[3] = pack2(b1.z, b1.w);
            float4 w0 = *(const float4*)&ws[k][8 * ty];
            float4 w1 = *(const float4*)&ws[k][8 * ty + 4];
            float wa[8] = {w0.x, w0.y, w0.z, w0.w, w1.x, w1.y, w1.z, w1.w};
#pragma unroll
            for (int i = 0; i < 8; i++) {
                u64 a2 = pack2(wa[i], wa[i]);
#pragma unroll
                for (int j = 0; j < 4; j++) ffma2(acc2[i][j], a2, bp[j]);
            }
        }
        __syncthreads();
    }

#pragma unroll
    for (int i = 0; i < 8; i++) {
        int    c    = c0 + 8 * ty + i;
        float  bv   = wb[c];
        size_t base = ((size_t)b * CC + c) * NP + n0 + 8 * tx;
        float4 xv0  = *(const float4*)&x[base];
        float4 xv1  = *(const float4*)&x[base + 4];
        float2 f0 = unpack2(acc2[i][0]);
        float2 f1 = unpack2(acc2[i][1]);
        float2 f2 = unpack2(acc2[i][2]);
        float2 f3 = unpack2(acc2[i][3]);
        float4 r0 = make_float4(f0.x + bv + xv0.x, f0.y + bv + xv0.y,
                                f1.x + bv + xv0.z, f1.y + bv + xv0.w);
        float4 r1 = make_float4(f2.x + bv + xv1.x, f2.y + bv + xv1.y,
                                f3.x + bv + xv1.z, f3.y + bv + xv1.w);
        *(float4*)&out[base]     = r0;
        *(float4*)&out[base + 4] = r1;
    }
}

// =================================================================
extern "C" void kernel_launch(void* const* d_in, const int* in_sizes, int n_in,
                              void* d_out, int out_size)
{
    const float* x  = (const float*)d_in[0];
    const float* tw = (const float*)d_in[1];
    const float* tb = (const float*)d_in[2];
    const float* pw = (const float*)d_in[3];
    const float* pb = (const float*)d_in[4];
    const float* gw = (const float*)d_in[5];
    const float* gb = (const float*)d_in[6];
    const float* ww = (const float*)d_in[7];
    const float* wb = (const float*)d_in[8];
    float* out = (float*)d_out;

    cudaFuncSetAttribute(attn_kernel, cudaFuncAttributeMaxDynamicSharedMemorySize, SMEM_ATTN);

    proj_kernel<<<dim3(NP / 128, BB, 3), 256>>>(x, tw, tb, pw, pb, gw, gb);
    attn_kernel<<<dim3(NP / 128, 2, BB), 128, SMEM_ATTN>>>();
    outproj_kernel<<<dim3(NP / 128, CC / 128, BB), 256>>>(x, ww, wb, out);
}

// round 7
// speedup vs baseline: 4.9991x; 1.1408x over previous
#include <cuda_runtime.h>
#include <cuda_fp16.h>
#include <math.h>
#include <stdint.h>

#define BB 4
#define CC 256
#define CI 128
#define NP 4096
#define LOG2E 1.4426950408889634f

typedef unsigned long long u64;
typedef unsigned int u32;

// Scratch (device globals: allocation-free rule)
__device__ __half g_xh[BB * CC * NP];  // x hi : (b, c, n)
__device__ __half g_xl[BB * CC * NP];  // x lo
__device__ __half g_twh[CI * CC], g_twl[CI * CC];
__device__ __half g_pwh[CI * CC], g_pwl[CI * CC];
__device__ __half g_gwh[CI * CC], g_gwl[CI * CC];
__device__ __half g_wwh[CC * CI], g_wwl[CC * CI];
__device__ __half g_qh[BB * NP * CI];  // theta(x)*log2e hi         : (b, n, o)
__device__ __half g_qc[BB * NP * CI];  // qh/64 + ql (correction)   : (b, n, o)
__device__ __half g_kh[BB * NP * CI];  // phi(x) hi                 : (b, m, o)
__device__ __half g_kc[BB * NP * CI];  // kh + 64*kl (correction)   : (b, m, o)
__device__ __half g_vt[BB * CI * NP];  // g(x) transposed           : (b, o, m)
__device__ float  g_po[2 * BB * NP * CI];  // unnormalized partial O per kv-split
__device__ float  g_pm[2 * BB * NP];       // partial running max (log2 domain)
__device__ float  g_pl[2 * BB * NP];       // partial running sum

// ---------------- helpers ----------------
__device__ __forceinline__ float ex2(float x) {
    float y;
    asm("ex2.approx.ftz.f32 %0, %1;" : "=f"(y) : "f"(x));
    return y;
}
__device__ __forceinline__ u32 smem_u32(const void* p) {
    u32 a;
    asm("{ .reg .u64 t; cvta.to.shared.u64 t, %1; cvt.u32.u64 %0, t; }" : "=r"(a) : "l"(p));
    return a;
}
__device__ __forceinline__ u32 h2u(__half a, __half b) {
    __half2 h = __halves2half2(a, b);
    return *(u32*)&h;
}

// ---------------- mma.sync / ldmatrix / cp.async ----------------
__device__ __forceinline__ void ldm4(u32& r0, u32& r1, u32& r2, u32& r3, u32 addr) {
    asm volatile("ldmatrix.sync.aligned.m8n8.x4.shared.b16 {%0,%1,%2,%3}, [%4];"
                 : "=r"(r0), "=r"(r1), "=r"(r2), "=r"(r3) : "r"(addr));
}
__device__ __forceinline__ void ldm4t(u32& r0, u32& r1, u32& r2, u32& r3, u32 addr) {
    asm volatile("ldmatrix.sync.aligned.m8n8.x4.trans.shared.b16 {%0,%1,%2,%3}, [%4];"
                 : "=r"(r0), "=r"(r1), "=r"(r2), "=r"(r3) : "r"(addr));
}
__device__ __forceinline__ void mma16816(float* c, u32 a0, u32 a1, u32 a2, u32 a3,
                                         u32 b0, u32 b1) {
    asm volatile(
        "mma.sync.aligned.m16n8k16.row.col.f32.f16.f16.f32 "
        "{%0,%1,%2,%3}, {%4,%5,%6,%7}, {%8,%9}, {%0,%1,%2,%3};"
        : "+f"(c[0]), "+f"(c[1]), "+f"(c[2]), "+f"(c[3])
        : "r"(a0), "r"(a1), "r"(a2), "r"(a3), "r"(b0), "r"(b1));
}
__device__ __forceinline__ void cpa(u32 s, const void* g) {
    asm volatile("cp.async.cg.shared.global [%0], [%1], 16;" :: "r"(s), "l"(g));
}
#define CP_COMMIT() asm volatile("cp.async.commit_group;")
#define CP_WAIT1()  asm volatile("cp.async.wait_group 1;")
#define CP_WAIT0()  asm volatile("cp.async.wait_group 0;")

#define SWZ256(x) ((x) ^ (((x) >> 4) & 0x70))   // 256B rows
#define SWZ128(x) ((x) ^ (((x) >> 3) & 0x70))   // 128B rows

// =================================================================
// Kernel 0: fp32 -> fp16 hi/lo conversion (x and weights).
// =================================================================
__global__ __launch_bounds__(256) void conv_hl(const float* __restrict__ src,
                                               __half* __restrict__ dh,
                                               __half* __restrict__ dl, int n)
{
    int i = (blockIdx.x * 256 + threadIdx.x) * 4;
    if (i >= n) return;
    float4 v = *(const float4*)&src[i];
    __half h0 = __float2half_rn(v.x), h1 = __float2half_rn(v.y);
    __half h2 = __float2half_rn(v.z), h3 = __float2half_rn(v.w);
    __half l0 = __float2half_rn(v.x - __half2float(h0));
    __half l1 = __float2half_rn(v.y - __half2float(h1));
    __half l2 = __float2half_rn(v.z - __half2float(h2));
    __half l3 = __float2half_rn(v.w - __half2float(h3));
    *(uint2*)&dh[i] = make_uint2(h2u(h0, h1), h2u(h2, h3));
    *(uint2*)&dl[i] = make_uint2(h2u(l0, l1), h2u(l2, l3));
}

// =================================================================
// Kernel 1: QKV projections on tensor cores, 3-pass fp16 hi/lo.
// y[n,o] = sum_c x[c,n]*W[o,c];  A = x^T via ldmatrix.trans, B = W.
// Tile 128n x 128o, k-chunks of 64. 8 warps = 4m x 2n.
// smem: xs_h 0..16K | xs_l 16..32K | ws_h 32..48K | ws_l 48..64K
// =================================================================
#define PJ_SMEM 65536

__global__ __launch_bounds__(256, 2) void proj_kernel(
    const float* __restrict__ tb, const float* __restrict__ pb,
    const float* __restrict__ gb)
{
    extern __shared__ char ps[];
    __shared__ float bias_s[128];
    const u32 s32 = smem_u32(ps);
    const int z  = blockIdx.z;
    const int b  = blockIdx.y;
    const int n0 = blockIdx.x * 128;
    const int t  = threadIdx.x;
    const int lane = t & 31;
    const int w  = t >> 5;
    const int wm = w & 3;      // m-tile (32 n-rows)
    const int wn = w >> 2;     // n-tile (64 o-cols)

    const int lrow = lane & 15;
    const int lcol = (lane >> 4) * 16;
    const int g    = lane >> 2;
    const int c2   = (lane & 3) * 2;
    // trans-ldmatrix lane addressing (A = x^T)
    const int trow = ((lane >> 4) << 3) + (lane & 7);   // k-row within 16
    const int tcol = ((lane >> 3) & 1) * 8;             // m-col offset (halves)

    const __half* Wh = (z == 0) ? g_twh : (z == 1) ? g_pwh : g_gwh;
    const __half* Wl = (z == 0) ? g_twl : (z == 1) ? g_pwl : g_gwl;
    const float*  bi = (z == 0) ? tb : (z == 1) ? pb : gb;
    const __half* Xh = g_xh + (size_t)b * CC * NP;
    const __half* Xl = g_xl + (size_t)b * CC * NP;

    if (t < 128) bias_s[t] = bi[t];

    float acc[2][8][4];
#pragma unroll
    for (int mf = 0; mf < 2; mf++)
#pragma unroll
        for (int nf = 0; nf < 8; nf++)
#pragma unroll
            for (int q = 0; q < 4; q++) acc[mf][nf][q] = 0.0f;

    for (int c0 = 0; c0 < CC; c0 += 64) {
        __syncthreads();
        // stage x chunk [64c][128n] h+l
#pragma unroll
        for (int i = 0; i < 4; i++) {
            int id = i * 256 + t;
            int row = id >> 4, ch = id & 15;
            u32 sw = SWZ256(row * 256 + ch * 16);
            cpa(s32 + sw,         Xh + (size_t)(c0 + row) * NP + n0 + ch * 8);
            cpa(s32 + 16384 + sw, Xl + (size_t)(c0 + row) * NP + n0 + ch * 8);
        }
        // stage w chunk [128o][64c] h+l
#pragma unroll
        for (int i = 0; i < 4; i++) {
            int id = i * 256 + t;
            int row = id >> 3, ch = id & 7;
            u32 sw = SWZ128(row * 128 + ch * 16);
            cpa(s32 + 32768 + sw, Wh + (size_t)row * CC + c0 + ch * 8);
            cpa(s32 + 49152 + sw, Wl + (size_t)row * CC + c0 + ch * 8);
        }
        CP_COMMIT();
        CP_WAIT0();
        __syncthreads();

#pragma unroll
        for (int kc = 0; kc < 4; kc++) {
            u32 A[2][4], B[4][4];
            // Ah
#pragma unroll
            for (int mf = 0; mf < 2; mf++)
                ldm4t(A[mf][0], A[mf][1], A[mf][2], A[mf][3],
                      s32 + SWZ256((kc * 16 + trow) * 256 + (wm * 32 + mf * 16 + tcol) * 2));
            // Bh
#pragma unroll
            for (int bf = 0; bf < 4; bf++)
                ldm4(B[bf][0], B[bf][1], B[bf][2], B[bf][3],
                     s32 + 32768 + SWZ128((wn * 64 + bf * 16 + lrow) * 128 + kc * 32 + lcol));
#pragma unroll
            for (int mf = 0; mf < 2; mf++)
#pragma unroll
                for (int bf = 0; bf < 4; bf++) {
                    mma16816(acc[mf][2 * bf],     A[mf][0], A[mf][1], A[mf][2], A[mf][3], B[bf][0], B[bf][2]);
                    mma16816(acc[mf][2 * bf + 1], A[mf][0], A[mf][1], A[mf][2], A[mf][3], B[bf][1], B[bf][3]);
                }
            // Al x Bh
#pragma unroll
            for (int mf = 0; mf < 2; mf++)
                ldm4t(A[mf][0], A[mf][1], A[mf][2], A[mf][3],
                      s32 + 16384 + SWZ256((kc * 16 + trow) * 256 + (wm * 32 + mf * 16 + tcol) * 2));
#pragma unroll
            for (int mf = 0; mf < 2; mf++)
#pragma unroll
                for (int bf = 0; bf < 4; bf++) {
                    mma16816(acc[mf][2 * bf],     A[mf][0], A[mf][1], A[mf][2], A[mf][3], B[bf][0], B[bf][2]);
                    mma16816(acc[mf][2 * bf + 1], A[mf][0], A[mf][1], A[mf][2], A[mf][3], B[bf][1], B[bf][3]);
                }
            // Ah x Bl
#pragma unroll
            for (int mf = 0; mf < 2; mf++)
                ldm4t(A[mf][0], A[mf][1], A[mf][2], A[mf][3],
                      s32 + SWZ256((kc * 16 + trow) * 256 + (wm * 32 + mf * 16 + tcol) * 2));
#pragma unroll
            for (int bf = 0; bf < 4; bf++)
                ldm4(B[bf][0], B[bf][1], B[bf][2], B[bf][3],
                     s32 + 49152 + SWZ128((wn * 64 + bf * 16 + lrow) * 128 + kc * 32 + lcol));
#pragma unroll
            for (int mf = 0; mf < 2; mf++)
#pragma unroll
                for (int bf = 0; bf < 4; bf++) {
                    mma16816(acc[mf][2 * bf],     A[mf][0], A[mf][1], A[mf][2], A[mf][3], B[bf][0], B[bf][2]);
                    mma16816(acc[mf][2 * bf + 1], A[mf][0], A[mf][1], A[mf][2], A[mf][3], B[bf][1], B[bf][3]);
                }
        }
    }
    __syncthreads();

    if (z == 2) {
        // V: stage transposed fp16 [o][n] in smem, then coalesced copy to g_vt
#pragma unroll
        for (int mf = 0; mf < 2; mf++) {
            int nl = wm * 32 + mf * 16 + g;
#pragma unroll
            for (int nf = 0; nf < 8; nf++) {
                int o = wn * 64 + nf * 8 + c2;
                __half h00 = __float2half_rn(acc[mf][nf][0] + bias_s[o]);
                __half h01 = __float2half_rn(acc[mf][nf][1] + bias_s[o + 1]);
                __half h10 = __float2half_rn(acc[mf][nf][2] + bias_s[o]);
                __half h11 = __float2half_rn(acc[mf][nf][3] + bias_s[o + 1]);
                *(__half*)(ps + (o * 128 + nl) * 2)           = h00;
                *(__half*)(ps + ((o + 1) * 128 + nl) * 2)     = h01;
                *(__half*)(ps + (o * 128 + nl + 8) * 2)       = h10;
                *(__half*)(ps + ((o + 1) * 128 + nl + 8) * 2) = h11;
            }
        }
        __syncthreads();
        int o = t >> 1, part = t & 1;
        __half* dst = g_vt + ((size_t)b * CI + o) * NP + n0 + part * 64;
#pragma unroll
        for (int k = 0; k < 8; k++)
            *(uint4*)&dst[k * 8] = *(uint4*)(ps + (o * 128 + part * 64 + k * 8) * 2);
    } else {
        __half* dh = (z == 0) ? g_qh : g_kh;
        __half* dc = (z == 0) ? g_qc : g_kc;
        const float sc = (z == 0) ? LOG2E : 1.0f;
        const size_t bq = (size_t)b * NP + n0;
#pragma unroll
        for (int mf = 0; mf < 2; mf++) {
            int nl = wm * 32 + mf * 16 + g;
#pragma unroll
            for (int nf = 0; nf < 8; nf++) {
                int o = wn * 64 + nf * 8 + c2;
                float bv0 = bias_s[o], bv1 = bias_s[o + 1];
                float v[4];
                v[0] = (acc[mf][nf][0] + bv0) * sc;
                v[1] = (acc[mf][nf][1] + bv1) * sc;
                v[2] = (acc[mf][nf][2] + bv0) * sc;
                v[3] = (acc[mf][nf][3] + bv1) * sc;
                __half hh[4], cc[4];
#pragma unroll
                for (int q = 0; q < 4; q++) {
                    __half h = __float2half_rn(v[q]);
                    float  hf = __half2float(h);
                    float  l  = v[q] - hf;
                    hh[q] = h;
                    cc[q] = (z == 0) ? __float2half_rn(hf * 0.015625f + l)
                                     : __float2half_rn(hf + 64.0f * l);
                }
                size_t i0 = (bq + nl) * CI + o;
                size_t i1 = i0 + (size_t)8 * CI;
                *(u32*)&dh[i0] = h2u(hh[0], hh[1]);
                *(u32*)&dc[i0] = h2u(cc[0], cc[1]);
                *(u32*)&dh[i1] = h2u(hh[2], hh[3]);
                *(u32*)&dc[i1] = h2u(cc[2], cc[3]);
            }
        }
    }
}

// =================================================================
// Kernel 2: flash attention, 128 threads/CTA (4 warps x 32 q-rows),
// 2-pass QK^T, KV-split 2, swizzled smem, 2 CTAs/SM.  (unchanged)
// =================================================================
#define OFF_QH 0
#define OFF_QC 32768
#define OFF_KH 65536
#define OFF_KC 81920
#define OFF_V  98304
#define SMEM_ATTN 114688
#define KV_TILES 32

__device__ __forceinline__ void load_k(u32 s32, int m0,
                                       const __half* gkh, const __half* gkc, int t)
{
#pragma unroll
    for (int i = 0; i < 8; i++) {
        int id = i * 128 + t;
        int row = id >> 4, c = id & 15;
        u32 sw = SWZ256(row * 256 + c * 16);
        cpa(s32 + OFF_KH + sw, gkh + (size_t)(m0 + row) * CI + c * 8);
        cpa(s32 + OFF_KC + sw, gkc + (size_t)(m0 + row) * CI + c * 8);
    }
}
__device__ __forceinline__ void load_v(u32 s32, int m0, const __half* gvt, int t)
{
#pragma unroll
    for (int i = 0; i < 8; i++) {
        int id = i * 128 + t;
        int row = id >> 3, c = id & 7;
        cpa(s32 + OFF_V + SWZ128(row * 128 + c * 16), gvt + (size_t)row * NP + m0 + c * 8);
    }
}

__global__ __launch_bounds__(128, 2) void attn_kernel()
{
    extern __shared__ __align__(128) char smem[];
    const u32 s32   = smem_u32(smem);
    const int t     = threadIdx.x;
    const int lane  = t & 31;
    const int wr    = (t >> 5) * 32;
    const int row0  = blockIdx.x * 128;
    const int split = blockIdx.y;
    const int b     = blockIdx.z;
    const int kv0   = split * (NP / 2);

    const int lrow = lane & 15;
    const int lcol = (lane >> 4) * 16;
    const int g    = lane >> 2;
    const int c2   = (lane & 3) * 2;

    const __half* gqh = g_qh + ((size_t)b * NP + row0) * CI;
    const __half* gqc = g_qc + ((size_t)b * NP + row0) * CI;
    const __half* gkh = g_kh + ((size_t)b * NP + kv0) * CI;
    const __half* gkc = g_kc + ((size_t)b * NP + kv0) * CI;
    const __half* gvt = g_vt + (size_t)b * CI * NP + kv0;

#pragma unroll
    for (int i = 0; i < 16; i++) {
        int id = i * 128 + t;
        int row = id >> 4, c = id & 15;
        u32 sw = SWZ256(row * 256 + c * 16);
        cpa(s32 + OFF_QH + sw, gqh + (size_t)row * CI + c * 8);
        cpa(s32 + OFF_QC + sw, gqc + (size_t)row * CI + c * 8);
    }
    load_k(s32, 0, gkh, gkc, t);
    CP_COMMIT();
    load_v(s32, 0, gvt, t);
    CP_COMMIT();

    float o[2][16][4];
#pragma unroll
    for (int mf = 0; mf < 2; mf++)
#pragma unroll
        for (int nf = 0; nf < 16; nf++)
#pragma unroll
            for (int q = 0; q < 4; q++) o[mf][nf][q] = 0.0f;
    float mrun[2][2] = {{-1e30f, -1e30f}, {-1e30f, -1e30f}};
    float lrun[2][2] = {{0.0f, 0.0f}, {0.0f, 0.0f}};

    for (int tile = 0; tile < KV_TILES; tile++) {
        CP_WAIT1();
        __syncthreads();

        float s[2][8][4];
#pragma unroll
        for (int mf = 0; mf < 2; mf++)
#pragma unroll
            for (int nf = 0; nf < 8; nf++)
#pragma unroll
                for (int q = 0; q < 4; q++) s[mf][nf][q] = 0.0f;

#pragma unroll
        for (int kc = 0; kc < 8; kc++) {
            u32 qa[2][4];
#pragma unroll
            for (int mf = 0; mf < 2; mf++)
                ldm4(qa[mf][0], qa[mf][1], qa[mf][2], qa[mf][3],
                     s32 + OFF_QH + SWZ256((wr + mf * 16 + lrow) * 256 + kc * 32 + lcol));
#pragma unroll
            for (int nb = 0; nb < 4; nb++) {
                u32 k0, k1, k2, k3;
                ldm4(k0, k1, k2, k3,
                     s32 + OFF_KH + SWZ256((nb * 16 + lrow) * 256 + kc * 32 + lcol));
#pragma unroll
                for (int mf = 0; mf < 2; mf++) {
                    mma16816(s[mf][2 * nb],     qa[mf][0], qa[mf][1], qa[mf][2], qa[mf][3], k0, k2);
                    mma16816(s[mf][2 * nb + 1], qa[mf][0], qa[mf][1], qa[mf][2], qa[mf][3], k1, k3);
                }
            }
        }
#pragma unroll
        for (int mf = 0; mf < 2; mf++)
#pragma unroll
            for (int nf = 0; nf < 8; nf++)
#pragma unroll
                for (int q = 0; q < 4; q++) s[mf][nf][q] *= 0.984375f;

#pragma unroll
        for (int kc = 0; kc < 8; kc++) {
            u32 qa[2][4];
#pragma unroll
            for (int mf = 0; mf < 2; mf++)
                ldm4(qa[mf][0], qa[mf][1], qa[mf][2], qa[mf][3],
                     s32 + OFF_QC + SWZ256((wr + mf * 16 + lrow) * 256 + kc * 32 + lcol));
#pragma unroll
            for (int nb = 0; nb < 4; nb++) {
                u32 k0, k1, k2, k3;
                ldm4(k0, k1, k2, k3,
                     s32 + OFF_KC + SWZ256((nb * 16 + lrow) * 256 + kc * 32 + lcol));
#pragma unroll
                for (int mf = 0; mf < 2; mf++) {
                    mma16816(s[mf][2 * nb],     qa[mf][0], qa[mf][1], qa[mf][2], qa[mf][3], k0, k2);
                    mma16816(s[mf][2 * nb + 1], qa[mf][0], qa[mf][1], qa[mf][2], qa[mf][3], k1, k3);
                }
            }
        }

        __syncthreads();
        if (tile + 1 < KV_TILES) load_k(s32, (tile + 1) * 64, gkh, gkc, t);
        CP_COMMIT();

        float corr[2][2];
        u32   p[2][4][4];
#pragma unroll
        for (int mf = 0; mf < 2; mf++) {
            float mx0 = fmaxf(s[mf][0][0], s[mf][0][1]);
            float mx1 = fmaxf(s[mf][0][2], s[mf][0][3]);
#pragma unroll
            for (int nf = 1; nf < 8; nf++) {
                mx0 = fmaxf(mx0, fmaxf(s[mf][nf][0], s[mf][nf][1]));
                mx1 = fmaxf(mx1, fmaxf(s[mf][nf][2], s[mf][nf][3]));
            }
            mx0 = fmaxf(mx0, __shfl_xor_sync(0xffffffffu, mx0, 1));
            mx0 = fmaxf(mx0, __shfl_xor_sync(0xffffffffu, mx0, 2));
            mx1 = fmaxf(mx1, __shfl_xor_sync(0xffffffffu, mx1, 1));
            mx1 = fmaxf(mx1, __shfl_xor_sync(0xffffffffu, mx1, 2));
            float mnew0 = fmaxf(mrun[mf][0], mx0);
            float mnew1 = fmaxf(mrun[mf][1], mx1);
            corr[mf][0] = ex2(mrun[mf][0] - mnew0);
            corr[mf][1] = ex2(mrun[mf][1] - mnew1);
            mrun[mf][0] = mnew0;
            mrun[mf][1] = mnew1;

            float ls0 = 0.0f, ls1 = 0.0f;
#pragma unroll
            for (int kc2 = 0; kc2 < 4; kc2++) {
#pragma unroll
                for (int half = 0; half < 2; half++) {
                    int nf = 2 * kc2 + half;
                    float e0 = ex2(s[mf][nf][0] - mnew0);
                    float e1 = ex2(s[mf][nf][1] - mnew0);
                    float e2 = ex2(s[mf][nf][2] - mnew1);
                    float e3 = ex2(s[mf][nf][3] - mnew1);
                    ls0 += e0 + e1;
                    ls1 += e2 + e3;
                    p[mf][kc2][2 * half]     = h2u(__float2half_rn(e0), __float2half_rn(e1));
                    p[mf][kc2][2 * half + 1] = h2u(__float2half_rn(e2), __float2half_rn(e3));
                }
            }
            ls0 += __shfl_xor_sync(0xffffffffu, ls0, 1);
            ls0 += __shfl_xor_sync(0xffffffffu, ls0, 2);
            ls1 += __shfl_xor_sync(0xffffffffu, ls1, 1);
            ls1 += __shfl_xor_sync(0xffffffffu, ls1, 2);
            lrun[mf][0] = lrun[mf][0] * corr[mf][0] + ls0;
            lrun[mf][1] = lrun[mf][1] * corr[mf][1] + ls1;
        }

        if (__any_sync(0xffffffffu,
                       fminf(fminf(corr[0][0], corr[0][1]),
                             fminf(corr[1][0], corr[1][1])) < 0.99999f)) {
#pragma unroll
            for (int mf = 0; mf < 2; mf++)
#pragma unroll
                for (int nf = 0; nf < 16; nf++) {
                    o[mf][nf][0] *= corr[mf][0]; o[mf][nf][1] *= corr[mf][0];
                    o[mf][nf][2] *= corr[mf][1]; o[mf][nf][3] *= corr[mf][1];
                }
        }

        CP_WAIT1();
        __syncthreads();

#pragma unroll
        for (int kc2 = 0; kc2 < 4; kc2++) {
#pragma unroll
            for (int dg = 0; dg < 8; dg++) {
                u32 v0, v1, v2, v3;
                ldm4(v0, v1, v2, v3,
                     s32 + OFF_V + SWZ128((dg * 16 + lrow) * 128 + kc2 * 32 + lcol));
#pragma unroll
                for (int mf = 0; mf < 2; mf++) {
                    mma16816(o[mf][2 * dg],
                             p[mf][kc2][0], p[mf][kc2][1], p[mf][kc2][2], p[mf][kc2][3], v0, v2);
                    mma16816(o[mf][2 * dg + 1],
                             p[mf][kc2][0], p[mf][kc2][1], p[mf][kc2][2], p[mf][kc2][3], v1, v3);
                }
            }
        }

        __syncthreads();
        if (tile + 1 < KV_TILES) load_v(s32, (tile + 1) * 64, gvt, t);
        CP_COMMIT();
    }

    float* po = g_po + ((size_t)(split * BB + b) * NP + row0 + wr) * CI;
    float* pm = g_pm + (size_t)(split * BB + b) * NP + row0 + wr;
    float* pl = g_pl + (size_t)(split * BB + b) * NP + row0 + wr;
#pragma unroll
    for (int mf = 0; mf < 2; mf++) {
        int r0 = mf * 16 + g;
#pragma unroll
        for (int nf = 0; nf < 16; nf++) {
            *(float2*)&po[(size_t)r0 * CI + nf * 8 + c2] =
                make_float2(o[mf][nf][0], o[mf][nf][1]);
            *(float2*)&po[(size_t)(r0 + 8) * CI + nf * 8 + c2] =
                make_float2(o[mf][nf][2], o[mf][nf][3]);
        }
        if ((lane & 3) == 0) {
            pm[r0] = mrun[mf][0]; pm[r0 + 8] = mrun[mf][1];
            pl[r0] = lrun[mf][0]; pl[r0 + 8] = lrun[mf][1];
        }
    }
}

// =================================================================
// Kernel 3: fused merge + output projection on tensor cores.
// out[c,n] = sum_o w[c,o]*merged[n,o] + wb[c] + x[c,n]
// A = merged (pixel-major, hi/lo built in staging), B = w hi/lo.
// Tile 128n x 128c, k-chunks of 64 over o. 8 warps = 4m x 2n.
// smem: mh 0..16K | ml 16..32K | wh 32..48K | wl 48..64K; os reuses all.
// =================================================================
__global__ __launch_bounds__(256, 2) void outproj_kernel(
    const float* __restrict__ x, const float* __restrict__ wb,
    float* __restrict__ out)
{
    extern __shared__ char ps[];
    __shared__ float wgt0[128], wgt1[128];
    const u32 s32 = smem_u32(ps);
    const int b  = blockIdx.z;
    const int cb = blockIdx.y * 128;
    const int n0 = blockIdx.x * 128;
    const int t  = threadIdx.x;
    const int lane = t & 31;
    const int w  = t >> 5;
    const int wm = w & 3;
    const int wn = w >> 2;
    const int lrow = lane & 15;
    const int lcol = (lane >> 4) * 16;
    const int g    = lane >> 2;
    const int c2   = (lane & 3) * 2;

    if (t < 128) {
        int bn = b * NP + n0 + t;
        float m0 = g_pm[bn], m1 = g_pm[BB * NP + bn];
        float l0 = g_pl[bn], l1 = g_pl[BB * NP + bn];
        float m  = fmaxf(m0, m1);
        float w0 = ex2(m0 - m), w1 = ex2(m1 - m);
        float inv = 1.0f / (w0 * l0 + w1 * l1);
        wgt0[t] = w0 * inv;
        wgt1[t] = w1 * inv;
    }
    __syncthreads();

    float acc[2][8][4];
#pragma unroll
    for (int mf = 0; mf < 2; mf++)
#pragma unroll
        for (int nf = 0; nf < 8; nf++)
#pragma unroll
            for (int q = 0; q < 4; q++) acc[mf][nf][q] = 0.0f;

    const float* p0 = g_po + ((size_t)b * NP + n0) * CI;
    const float* p1 = g_po + ((size_t)(BB + b) * NP + n0) * CI;

    for (int o0 = 0; o0 < CI; o0 += 64) {
        __syncthreads();
        // stage merged A [128n][64o] hi/lo
#pragma unroll
        for (int i = 0; i < 8; i++) {
            int id = i * 256 + t;
            int row = id >> 4, ch = id & 15;   // ch = o-quad (4 f32)
            float4 a = *(const float4*)&p0[(size_t)row * CI + o0 + ch * 4];
            float4 c = *(const float4*)&p1[(size_t)row * CI + o0 + ch * 4];
            float w0 = wgt0[row], w1 = wgt1[row];
            float m[4] = {a.x * w0 + c.x * w1, a.y * w0 + c.y * w1,
                          a.z * w0 + c.z * w1, a.w * w0 + c.w * w1};
            __half h[4], l[4];
#pragma unroll
            for (int q = 0; q < 4; q++) {
                h[q] = __float2half_rn(m[q]);
                l[q] = __float2half_rn(m[q] - __half2float(h[q]));
            }
            u32 sw = SWZ128(row * 128 + ch * 8);
            *(uint2*)(ps + sw)         = make_uint2(h2u(h[0], h[1]), h2u(h[2], h[3]));
            *(uint2*)(ps + 16384 + sw) = make_uint2(h2u(l[0], l[1]), h2u(l[2], l[3]));
        }
        // stage w chunk [128c][64o] hi/lo
#pragma unroll
        for (int i = 0; i < 4; i++) {
            int id = i * 256 + t;
            int row = id >> 3, ch = id & 7;
            u32 sw = SWZ128(row * 128 + ch * 16);
            cpa(s32 + 32768 + sw, g_wwh + (size_t)(cb + row) * CI + o0 + ch * 8);
            cpa(s32 + 49152 + sw, g_wwl + (size_t)(cb + row) * CI + o0 + ch * 8);
        }
        CP_COMMIT();
        CP_WAIT0();
        __syncthreads();

#pragma unroll
        for (int kc = 0; kc < 4; kc++) {
            u32 A[2][4], B[4][4];
#pragma unroll
            for (int mf = 0; mf < 2; mf++)
                ldm4(A[mf][0], A[mf][1], A[mf][2], A[mf][3],
                     s32 + SWZ128((wm * 32 + mf * 16 + lrow) * 128 + kc * 32 + lcol));
#pragma unroll
            for (int bf = 0; bf < 4; bf++)
                ldm4(B[bf][0], B[bf][1], B[bf][2], B[bf][3],
                     s32 + 32768 + SWZ128((wn * 64 + bf * 16 + lrow) * 128 + kc * 32 + lcol));
#pragma unroll
            for (int mf = 0; mf < 2; mf++)
#pragma unroll
                for (int bf = 0; bf < 4; bf++) {
                    mma16816(acc[mf][2 * bf],     A[mf][0], A[mf][1], A[mf][2], A[mf][3], B[bf][0], B[bf][2]);
                    mma16816(acc[mf][2 * bf + 1], A[mf][0], A[mf][1], A[mf][2], A[mf][3], B[bf][1], B[bf][3]);
                }
#pragma unroll
            for (int mf = 0; mf < 2; mf++)
                ldm4(A[mf][0], A[mf][1], A[mf][2], A[mf][3],
                     s32 + 16384 + SWZ128((wm * 32 + mf * 16 + lrow) * 128 + kc * 32 + lcol));
#pragma unroll
            for (int mf = 0; mf < 2; mf++)
#pragma unroll
                for (int bf = 0; bf < 4; bf++) {
                    mma16816(acc[mf][2 * bf],     A[mf][0], A[mf][1], A[mf][2], A[mf][3], B[bf][0], B[bf][2]);
                    mma16816(acc[mf][2 * bf + 1], A[mf][0], A[mf][1], A[mf][2], A[mf][3], B[bf][1], B[bf][3]);
                }
#pragma unroll
            for (int mf = 0; mf < 2; mf++)
                ldm4(A[mf][0], A[mf][1], A[mf][2], A[mf][3],
                     s32 + SWZ128((wm * 32 + mf * 16 + lrow) * 128 + kc * 32 + lcol));
#pragma unroll
            for (int bf = 0; bf < 4; bf++)
                ldm4(B[bf][0], B[bf][1], B[bf][2], B[bf][3],
                     s32 + 49152 + SWZ128((wn * 64 + bf * 16 + lrow) * 128 + kc * 32 + lcol));
#pragma unroll
            for (int mf = 0; mf < 2; mf++)
#pragma unroll
                for (int bf = 0; bf < 4; bf++) {
                    mma16816(acc[mf][2 * bf],     A[mf][0], A[mf][1], A[mf][2], A[mf][3], B[bf][0], B[bf][2]);
                    mma16816(acc[mf][2 * bf + 1], A[mf][0], A[mf][1], A[mf][2], A[mf][3], B[bf][1], B[bf][3]);
                }
        }
    }
    __syncthreads();

    // stage D as os[c][n] f32 (64KB, reuses whole smem)
#pragma unroll
    for (int mf = 0; mf < 2; mf++) {
        int nl = wm * 32 + mf * 16 + g;
#pragma unroll
        for (int nf = 0; nf < 8; nf++) {
            int cl = wn * 64 + nf * 8 + c2;
            *(float*)(ps + (cl * 128 + nl) * 4)           = acc[mf][nf][0];
            *(float*)(ps + ((cl + 1) * 128 + nl) * 4)     = acc[mf][nf][1];
            *(float*)(ps + (cl * 128 + nl + 8) * 4)       = acc[mf][nf][2];
            *(float*)(ps + ((cl + 1) * 128 + nl + 8) * 4) = acc[mf][nf][3];
        }
    }
    __syncthreads();

    int r = t >> 1, part = t & 1;
    float bv = wb[cb + r];
    size_t base = ((size_t)b * CC + cb + r) * NP + n0 + part * 64;
#pragma unroll
    for (int k = 0; k < 16; k++) {
        float4 v  = *(float4*)(ps + (r * 128 + part * 64 + k * 4) * 4);
        float4 xv = *(const float4*)&x[base + k * 4];
        float4 rr = make_float4(v.x + bv + xv.x, v.y + bv + xv.y,
                                v.z + bv + xv.z, v.w + bv + xv.w);
        *(float4*)&out[base + k * 4] = rr;
    }
}

// =================================================================
extern "C" void kernel_launch(void* const* d_in, const int* in_sizes, int n_in,
                              void* d_out, int out_size)
{
    const float* x  = (const float*)d_in[0];
    const float* tw = (const float*)d_in[1];
    const float* tb = (const float*)d_in[2];
    const float* pw = (const float*)d_in[3];
    const float* pb = (const float*)d_in[4];
    const float* gw = (const float*)d_in[5];
    const float* gb = (const float*)d_in[6];
    const float* ww = (const float*)d_in[7];
    const float* wb = (const float*)d_in[8];
    float* out = (float*)d_out;

    cudaFuncSetAttribute(attn_kernel,    cudaFuncAttributeMaxDynamicSharedMemorySize, SMEM_ATTN);
    cudaFuncSetAttribute(proj_kernel,    cudaFuncAttributeMaxDynamicSharedMemorySize, PJ_SMEM);
    cudaFuncSetAttribute(outproj_kernel, cudaFuncAttributeMaxDynamicSharedMemorySize, PJ_SMEM);

    __half *xh, *xl, *twh, *twl, *pwh, *pwl, *gwh, *gwl, *wwh, *wwl;
    cudaGetSymbolAddress((void**)&xh,  g_xh);  cudaGetSymbolAddress((void**)&xl,  g_xl);
    cudaGetSymbolAddress((void**)&twh, g_twh); cudaGetSymbolAddress((void**)&twl, g_twl);
    cudaGetSymbolAddress((void**)&pwh, g_pwh); cudaGetSymbolAddress((void**)&pwl, g_pwl);
    cudaGetSymbolAddress((void**)&gwh, g_gwh); cudaGetSymbolAddress((void**)&gwl, g_gwl);
    cudaGetSymbolAddress((void**)&wwh, g_wwh); cudaGetSymbolAddress((void**)&wwl, g_wwl);

    conv_hl<<<BB * CC * NP / 1024, 256>>>(x, xh, xl, BB * CC * NP);
    conv_hl<<<CI * CC / 1024, 256>>>(tw, twh, twl, CI * CC);
    conv_hl<<<CI * CC / 1024, 256>>>(pw, pwh, pwl, CI * CC);
    conv_hl<<<CI * CC / 1024, 256>>>(gw, gwh, gwl, CI * CC);
    conv_hl<<<CC * CI / 1024, 256>>>(ww, wwh, wwl, CC * CI);

    proj_kernel<<<dim3(NP / 128, BB, 3), 256, PJ_SMEM>>>(tb, pb, gb);
    attn_kernel<<<dim3(NP / 128, 2, BB), 128, SMEM_ATTN>>>();
    outproj_kernel<<<dim3(NP / 128, CC / 128, BB), 256, PJ_SMEM>>>(x, wb, out);
}

// round 8
// speedup vs baseline: 5.2091x; 1.0420x over previous
#include <cuda_runtime.h>
#include <cuda_fp16.h>
#include <math.h>
#include <stdint.h>

#define BB 4
#define CC 256
#define CI 128
#define NP 4096
#define LOG2E 1.4426950408889634f

typedef unsigned long long u64;
typedef unsigned int u32;

// Scratch (device globals: allocation-free rule)
__device__ __half g_xh[BB * CC * NP];  // x hi : (b, c, n)
__device__ __half g_xl[BB * CC * NP];  // x lo
__device__ __half g_twh[CI * CC], g_twl[CI * CC];
__device__ __half g_pwh[CI * CC], g_pwl[CI * CC];
__device__ __half g_gwh[CI * CC], g_gwl[CI * CC];
__device__ __half g_wwh[CC * CI], g_wwl[CC * CI];
__device__ __half g_qh[BB * NP * CI];  // theta(x)*log2e hi         : (b, n, o)
__device__ __half g_qc[BB * NP * CI];  // qh/64 + ql (correction)   : (b, n, o)
__device__ __half g_kh[BB * NP * CI];  // phi(x) hi                 : (b, m, o)
__device__ __half g_kc[BB * NP * CI];  // kh + 64*kl (correction)   : (b, m, o)
__device__ __half g_vt[BB * CI * NP];  // g(x) transposed           : (b, o, m)
__device__ float  g_po[2 * BB * NP * CI];  // unnormalized partial O per kv-split
__device__ float  g_pm[2 * BB * NP];       // partial running max (log2 domain)
__device__ float  g_pl[2 * BB * NP];       // partial running sum

// ---------------- helpers ----------------
__device__ __forceinline__ float ex2(float x) {
    float y;
    asm("ex2.approx.ftz.f32 %0, %1;" : "=f"(y) : "f"(x));
    return y;
}
__device__ __forceinline__ u32 smem_u32(const void* p) {
    u32 a;
    asm("{ .reg .u64 t; cvta.to.shared.u64 t, %1; cvt.u32.u64 %0, t; }" : "=r"(a) : "l"(p));
    return a;
}
__device__ __forceinline__ u32 h2u(__half a, __half b) {
    __half2 h = __halves2half2(a, b);
    return *(u32*)&h;
}

// ---------------- mma.sync / ldmatrix / cp.async ----------------
__device__ __forceinline__ void ldm4(u32& r0, u32& r1, u32& r2, u32& r3, u32 addr) {
    asm volatile("ldmatrix.sync.aligned.m8n8.x4.shared.b16 {%0,%1,%2,%3}, [%4];"
                 : "=r"(r0), "=r"(r1), "=r"(r2), "=r"(r3) : "r"(addr));
}
__device__ __forceinline__ void ldm4t(u32& r0, u32& r1, u32& r2, u32& r3, u32 addr) {
    asm volatile("ldmatrix.sync.aligned.m8n8.x4.trans.shared.b16 {%0,%1,%2,%3}, [%4];"
                 : "=r"(r0), "=r"(r1), "=r"(r2), "=r"(r3) : "r"(addr));
}
__device__ __forceinline__ void mma16816(float* c, u32 a0, u32 a1, u32 a2, u32 a3,
                                         u32 b0, u32 b1) {
    asm volatile(
        "mma.sync.aligned.m16n8k16.row.col.f32.f16.f16.f32 "
        "{%0,%1,%2,%3}, {%4,%5,%6,%7}, {%8,%9}, {%0,%1,%2,%3};"
        : "+f"(c[0]), "+f"(c[1]), "+f"(c[2]), "+f"(c[3])
        : "r"(a0), "r"(a1), "r"(a2), "r"(a3), "r"(b0), "r"(b1));
}
__device__ __forceinline__ void cpa(u32 s, const void* g) {
    asm volatile("cp.async.cg.shared.global [%0], [%1], 16;" :: "r"(s), "l"(g));
}
#define CP_COMMIT() asm volatile("cp.async.commit_group;")
#define CP_WAIT1()  asm volatile("cp.async.wait_group 1;")
#define CP_WAIT0()  asm volatile("cp.async.wait_group 0;")

#define SWZ256(x) ((x) ^ (((x) >> 4) & 0x70))   // 256B rows
#define SWZ128(x) ((x) ^ (((x) >> 3) & 0x70))   // 128B rows

#define HONE 0x3C003C00u   // half2(1.0, 1.0)

// =================================================================
// Kernel 0: fp32 -> fp16 hi/lo conversion, single launch for x + 4 weights.
// blocks [0, 4096): x ; then 32 blocks each for tw, pw, gw, ww.
// =================================================================
__global__ __launch_bounds__(256) void conv_all(
    const float* __restrict__ x,
    const float* __restrict__ tw, const float* __restrict__ pw,
    const float* __restrict__ gw, const float* __restrict__ ww)
{
    int bid = blockIdx.x;
    const float* src;
    __half *dh, *dl;
    int i;
    if (bid < 4096) {
        src = x; dh = g_xh; dl = g_xl;
        i = bid * 1024 + threadIdx.x * 4;
    } else {
        int wsel = (bid - 4096) >> 5;
        i = ((bid - 4096) & 31) * 1024 + threadIdx.x * 4;
        src = (wsel == 0) ? tw : (wsel == 1) ? pw : (wsel == 2) ? gw : ww;
        dh  = (wsel == 0) ? g_twh : (wsel == 1) ? g_pwh : (wsel == 2) ? g_gwh : g_wwh;
        dl  = (wsel == 0) ? g_twl : (wsel == 1) ? g_pwl : (wsel == 2) ? g_gwl : g_wwl;
    }
    float4 v = *(const float4*)&src[i];
    __half h0 = __float2half_rn(v.x), h1 = __float2half_rn(v.y);
    __half h2 = __float2half_rn(v.z), h3 = __float2half_rn(v.w);
    __half l0 = __float2half_rn(v.x - __half2float(h0));
    __half l1 = __float2half_rn(v.y - __half2float(h1));
    __half l2 = __float2half_rn(v.z - __half2float(h2));
    __half l3 = __float2half_rn(v.w - __half2float(h3));
    *(uint2*)&dh[i] = make_uint2(h2u(h0, h1), h2u(h2, h3));
    *(uint2*)&dl[i] = make_uint2(h2u(l0, l1), h2u(l2, l3));
}

// =================================================================
// Kernel 1: QKV projections on tensor cores, 3-pass fp16 hi/lo.
// y[n,o] = sum_c x[c,n]*W[o,c];  A = x^T via ldmatrix.trans, B = W.
// Tile 128n x 128o, k-chunks of 64. 8 warps = 4m x 2n.
// =================================================================
#define PJ_SMEM 65536

__global__ __launch_bounds__(256, 2) void proj_kernel(
    const float* __restrict__ tb, const float* __restrict__ pb,
    const float* __restrict__ gb)
{
    extern __shared__ char ps[];
    __shared__ float bias_s[128];
    const u32 s32 = smem_u32(ps);
    const int z  = blockIdx.z;
    const int b  = blockIdx.y;
    const int n0 = blockIdx.x * 128;
    const int t  = threadIdx.x;
    const int lane = t & 31;
    const int w  = t >> 5;
    const int wm = w & 3;
    const int wn = w >> 2;

    const int lrow = lane & 15;
    const int lcol = (lane >> 4) * 16;
    const int g    = lane >> 2;
    const int c2   = (lane & 3) * 2;
    const int trow = ((lane >> 4) << 3) + (lane & 7);
    const int tcol = ((lane >> 3) & 1) * 8;

    const __half* Wh = (z == 0) ? g_twh : (z == 1) ? g_pwh : g_gwh;
    const __half* Wl = (z == 0) ? g_twl : (z == 1) ? g_pwl : g_gwl;
    const float*  bi = (z == 0) ? tb : (z == 1) ? pb : gb;
    const __half* Xh = g_xh + (size_t)b * CC * NP;
    const __half* Xl = g_xl + (size_t)b * CC * NP;

    if (t < 128) bias_s[t] = bi[t];

    float acc[2][8][4];
#pragma unroll
    for (int mf = 0; mf < 2; mf++)
#pragma unroll
        for (int nf = 0; nf < 8; nf++)
#pragma unroll
            for (int q = 0; q < 4; q++) acc[mf][nf][q] = 0.0f;

    for (int c0 = 0; c0 < CC; c0 += 64) {
        __syncthreads();
#pragma unroll
        for (int i = 0; i < 4; i++) {
            int id = i * 256 + t;
            int row = id >> 4, ch = id & 15;
            u32 sw = SWZ256(row * 256 + ch * 16);
            cpa(s32 + sw,         Xh + (size_t)(c0 + row) * NP + n0 + ch * 8);
            cpa(s32 + 16384 + sw, Xl + (size_t)(c0 + row) * NP + n0 + ch * 8);
        }
#pragma unroll
        for (int i = 0; i < 4; i++) {
            int id = i * 256 + t;
            int row = id >> 3, ch = id & 7;
            u32 sw = SWZ128(row * 128 + ch * 16);
            cpa(s32 + 32768 + sw, Wh + (size_t)row * CC + c0 + ch * 8);
            cpa(s32 + 49152 + sw, Wl + (size_t)row * CC + c0 + ch * 8);
        }
        CP_COMMIT();
        CP_WAIT0();
        __syncthreads();

#pragma unroll
        for (int kc = 0; kc < 4; kc++) {
            u32 Ah[2][4], Al[2][4], B[4][4];
            // Ah (kept live for pass 3)
#pragma unroll
            for (int mf = 0; mf < 2; mf++)
                ldm4t(Ah[mf][0], Ah[mf][1], Ah[mf][2], Ah[mf][3],
                      s32 + SWZ256((kc * 16 + trow) * 256 + (wm * 32 + mf * 16 + tcol) * 2));
            // Bh
#pragma unroll
            for (int bf = 0; bf < 4; bf++)
                ldm4(B[bf][0], B[bf][1], B[bf][2], B[bf][3],
                     s32 + 32768 + SWZ128((wn * 64 + bf * 16 + lrow) * 128 + kc * 32 + lcol));
#pragma unroll
            for (int mf = 0; mf < 2; mf++)
#pragma unroll
                for (int bf = 0; bf < 4; bf++) {
                    mma16816(acc[mf][2 * bf],     Ah[mf][0], Ah[mf][1], Ah[mf][2], Ah[mf][3], B[bf][0], B[bf][2]);
                    mma16816(acc[mf][2 * bf + 1], Ah[mf][0], Ah[mf][1], Ah[mf][2], Ah[mf][3], B[bf][1], B[bf][3]);
                }
            // Al x Bh
#pragma unroll
            for (int mf = 0; mf < 2; mf++)
                ldm4t(Al[mf][0], Al[mf][1], Al[mf][2], Al[mf][3],
                      s32 + 16384 + SWZ256((kc * 16 + trow) * 256 + (wm * 32 + mf * 16 + tcol) * 2));
#pragma unroll
            for (int mf = 0; mf < 2; mf++)
#pragma unroll
                for (int bf = 0; bf < 4; bf++) {
                    mma16816(acc[mf][2 * bf],     Al[mf][0], Al[mf][1], Al[mf][2], Al[mf][3], B[bf][0], B[bf][2]);
                    mma16816(acc[mf][2 * bf + 1], Al[mf][0], Al[mf][1], Al[mf][2], Al[mf][3], B[bf][1], B[bf][3]);
                }
            // Ah x Bl (Ah reused from registers)
#pragma unroll
            for (int bf = 0; bf < 4; bf++)
                ldm4(B[bf][0], B[bf][1], B[bf][2], B[bf][3],
                     s32 + 49152 + SWZ128((wn * 64 + bf * 16 + lrow) * 128 + kc * 32 + lcol));
#pragma unroll
            for (int mf = 0; mf < 2; mf++)
#pragma unroll
                for (int bf = 0; bf < 4; bf++) {
                    mma16816(acc[mf][2 * bf],     Ah[mf][0], Ah[mf][1], Ah[mf][2], Ah[mf][3], B[bf][0], B[bf][2]);
                    mma16816(acc[mf][2 * bf + 1], Ah[mf][0], Ah[mf][1], Ah[mf][2], Ah[mf][3], B[bf][1], B[bf][3]);
                }
        }
    }
    __syncthreads();

    if (z == 2) {
#pragma unroll
        for (int mf = 0; mf < 2; mf++) {
            int nl = wm * 32 + mf * 16 + g;
#pragma unroll
            for (int nf = 0; nf < 8; nf++) {
                int o = wn * 64 + nf * 8 + c2;
                __half h00 = __float2half_rn(acc[mf][nf][0] + bias_s[o]);
                __half h01 = __float2half_rn(acc[mf][nf][1] + bias_s[o + 1]);
                __half h10 = __float2half_rn(acc[mf][nf][2] + bias_s[o]);
                __half h11 = __float2half_rn(acc[mf][nf][3] + bias_s[o + 1]);
                *(__half*)(ps + (o * 128 + nl) * 2)           = h00;
                *(__half*)(ps + ((o + 1) * 128 + nl) * 2)     = h01;
                *(__half*)(ps + (o * 128 + nl + 8) * 2)       = h10;
                *(__half*)(ps + ((o + 1) * 128 + nl + 8) * 2) = h11;
            }
        }
        __syncthreads();
        int o = t >> 1, part = t & 1;
        __half* dst = g_vt + ((size_t)b * CI + o) * NP + n0 + part * 64;
#pragma unroll
        for (int k = 0; k < 8; k++)
            *(uint4*)&dst[k * 8] = *(uint4*)(ps + (o * 128 + part * 64 + k * 8) * 2);
    } else {
        __half* dh = (z == 0) ? g_qh : g_kh;
        __half* dc = (z == 0) ? g_qc : g_kc;
        const float sc = (z == 0) ? LOG2E : 1.0f;
        const size_t bq = (size_t)b * NP + n0;
#pragma unroll
        for (int mf = 0; mf < 2; mf++) {
            int nl = wm * 32 + mf * 16 + g;
#pragma unroll
            for (int nf = 0; nf < 8; nf++) {
                int o = wn * 64 + nf * 8 + c2;
                float bv0 = bias_s[o], bv1 = bias_s[o + 1];
                float v[4];
                v[0] = (acc[mf][nf][0] + bv0) * sc;
                v[1] = (acc[mf][nf][1] + bv1) * sc;
                v[2] = (acc[mf][nf][2] + bv0) * sc;
                v[3] = (acc[mf][nf][3] + bv1) * sc;
                __half hh[4], cc[4];
#pragma unroll
                for (int q = 0; q < 4; q++) {
                    __half h = __float2half_rn(v[q]);
                    float  hf = __half2float(h);
                    float  l  = v[q] - hf;
                    hh[q] = h;
                    cc[q] = (z == 0) ? __float2half_rn(hf * 0.015625f + l)
                                     : __float2half_rn(hf + 64.0f * l);
                }
                size_t i0 = (bq + nl) * CI + o;
                size_t i1 = i0 + (size_t)8 * CI;
                *(u32*)&dh[i0] = h2u(hh[0], hh[1]);
                *(u32*)&dc[i0] = h2u(cc[0], cc[1]);
                *(u32*)&dh[i1] = h2u(hh[2], hh[3]);
                *(u32*)&dc[i1] = h2u(cc[2], cc[3]);
            }
        }
    }
}

// =================================================================
// Kernel 2: flash attention, 128 threads/CTA (4 warps x 32 q-rows),
// 2-pass QK^T, KV-split 2, swizzled smem, 2 CTAs/SM.
// l computed via ones-MMA on the fp16 P fragments (tensor pipe).
// =================================================================
#define OFF_QH 0
#define OFF_QC 32768
#define OFF_KH 65536
#define OFF_KC 81920
#define OFF_V  98304
#define SMEM_ATTN 114688
#define KV_TILES 32

__device__ __forceinline__ void load_k(u32 s32, int m0,
                                       const __half* gkh, const __half* gkc, int t)
{
#pragma unroll
    for (int i = 0; i < 8; i++) {
        int id = i * 128 + t;
        int row = id >> 4, c = id & 15;
        u32 sw = SWZ256(row * 256 + c * 16);
        cpa(s32 + OFF_KH + sw, gkh + (size_t)(m0 + row) * CI + c * 8);
        cpa(s32 + OFF_KC + sw, gkc + (size_t)(m0 + row) * CI + c * 8);
    }
}
__device__ __forceinline__ void load_v(u32 s32, int m0, const __half* gvt, int t)
{
#pragma unroll
    for (int i = 0; i < 8; i++) {
        int id = i * 128 + t;
        int row = id >> 3, c = id & 7;
        cpa(s32 + OFF_V + SWZ128(row * 128 + c * 16), gvt + (size_t)row * NP + m0 + c * 8);
    }
}

__global__ __launch_bounds__(128, 2) void attn_kernel()
{
    extern __shared__ __align__(128) char smem[];
    const u32 s32   = smem_u32(smem);
    const int t     = threadIdx.x;
    const int lane  = t & 31;
    const int wr    = (t >> 5) * 32;
    const int row0  = blockIdx.x * 128;
    const int split = blockIdx.y;
    const int b     = blockIdx.z;
    const int kv0   = split * (NP / 2);

    const int lrow = lane & 15;
    const int lcol = (lane >> 4) * 16;
    const int g    = lane >> 2;
    const int c2   = (lane & 3) * 2;

    const __half* gqh = g_qh + ((size_t)b * NP + row0) * CI;
    const __half* gqc = g_qc + ((size_t)b * NP + row0) * CI;
    const __half* gkh = g_kh + ((size_t)b * NP + kv0) * CI;
    const __half* gkc = g_kc + ((size_t)b * NP + kv0) * CI;
    const __half* gvt = g_vt + (size_t)b * CI * NP + kv0;

#pragma unroll
    for (int i = 0; i < 16; i++) {
        int id = i * 128 + t;
        int row = id >> 4, c = id & 15;
        u32 sw = SWZ256(row * 256 + c * 16);
        cpa(s32 + OFF_QH + sw, gqh + (size_t)row * CI + c * 8);
        cpa(s32 + OFF_QC + sw, gqc + (size_t)row * CI + c * 8);
    }
    load_k(s32, 0, gkh, gkc, t);
    CP_COMMIT();
    load_v(s32, 0, gvt, t);
    CP_COMMIT();

    float o[2][16][4];
#pragma unroll
    for (int mf = 0; mf < 2; mf++)
#pragma unroll
        for (int nf = 0; nf < 16; nf++)
#pragma unroll
            for (int q = 0; q < 4; q++) o[mf][nf][q] = 0.0f;
    float mrun[2][2] = {{-1e30f, -1e30f}, {-1e30f, -1e30f}};
    float lrun[2][2] = {{0.0f, 0.0f}, {0.0f, 0.0f}};

    for (int tile = 0; tile < KV_TILES; tile++) {
        CP_WAIT1();
        __syncthreads();

        float s[2][8][4];
#pragma unroll
        for (int mf = 0; mf < 2; mf++)
#pragma unroll
            for (int nf = 0; nf < 8; nf++)
#pragma unroll
                for (int q = 0; q < 4; q++) s[mf][nf][q] = 0.0f;

#pragma unroll
        for (int kc = 0; kc < 8; kc++) {
            u32 qa[2][4];
#pragma unroll
            for (int mf = 0; mf < 2; mf++)
                ldm4(qa[mf][0], qa[mf][1], qa[mf][2], qa[mf][3],
                     s32 + OFF_QH + SWZ256((wr + mf * 16 + lrow) * 256 + kc * 32 + lcol));
#pragma unroll
            for (int nb = 0; nb < 4; nb++) {
                u32 k0, k1, k2, k3;
                ldm4(k0, k1, k2, k3,
                     s32 + OFF_KH + SWZ256((nb * 16 + lrow) * 256 + kc * 32 + lcol));
#pragma unroll
                for (int mf = 0; mf < 2; mf++) {
                    mma16816(s[mf][2 * nb],     qa[mf][0], qa[mf][1], qa[mf][2], qa[mf][3], k0, k2);
                    mma16816(s[mf][2 * nb + 1], qa[mf][0], qa[mf][1], qa[mf][2], qa[mf][3], k1, k3);
                }
            }
        }
#pragma unroll
        for (int mf = 0; mf < 2; mf++)
#pragma unroll
            for (int nf = 0; nf < 8; nf++)
#pragma unroll
                for (int q = 0; q < 4; q++) s[mf][nf][q] *= 0.984375f;

#pragma unroll
        for (int kc = 0; kc < 8; kc++) {
            u32 qa[2][4];
#pragma unroll
            for (int mf = 0; mf < 2; mf++)
                ldm4(qa[mf][0], qa[mf][1], qa[mf][2], qa[mf][3],
                     s32 + OFF_QC + SWZ256((wr + mf * 16 + lrow) * 256 + kc * 32 + lcol));
#pragma unroll
            for (int nb = 0; nb < 4; nb++) {
                u32 k0, k1, k2, k3;
                ldm4(k0, k1, k2, k3,
                     s32 + OFF_KC + SWZ256((nb * 16 + lrow) * 256 + kc * 32 + lcol));
#pragma unroll
                for (int mf = 0; mf < 2; mf++) {
                    mma16816(s[mf][2 * nb],     qa[mf][0], qa[mf][1], qa[mf][2], qa[mf][3], k0, k2);
                    mma16816(s[mf][2 * nb + 1], qa[mf][0], qa[mf][1], qa[mf][2], qa[mf][3], k1, k3);
                }
            }
        }

        __syncthreads();
        if (tile + 1 < KV_TILES) load_k(s32, (tile + 1) * 64, gkh, gkc, t);
        CP_COMMIT();

        // ---- online softmax (l via ones-MMA below) ----
        float corr[2][2];
        u32   p[2][4][4];
#pragma unroll
        for (int mf = 0; mf < 2; mf++) {
            float mx0 = fmaxf(s[mf][0][0], s[mf][0][1]);
            float mx1 = fmaxf(s[mf][0][2], s[mf][0][3]);
#pragma unroll
            for (int nf = 1; nf < 8; nf++) {
                mx0 = fmaxf(mx0, fmaxf(s[mf][nf][0], s[mf][nf][1]));
                mx1 = fmaxf(mx1, fmaxf(s[mf][nf][2], s[mf][nf][3]));
            }
            mx0 = fmaxf(mx0, __shfl_xor_sync(0xffffffffu, mx0, 1));
            mx0 = fmaxf(mx0, __shfl_xor_sync(0xffffffffu, mx0, 2));
            mx1 = fmaxf(mx1, __shfl_xor_sync(0xffffffffu, mx1, 1));
            mx1 = fmaxf(mx1, __shfl_xor_sync(0xffffffffu, mx1, 2));
            float mnew0 = fmaxf(mrun[mf][0], mx0);
            float mnew1 = fmaxf(mrun[mf][1], mx1);
            corr[mf][0] = ex2(mrun[mf][0] - mnew0);
            corr[mf][1] = ex2(mrun[mf][1] - mnew1);
            mrun[mf][0] = mnew0;
            mrun[mf][1] = mnew1;

#pragma unroll
            for (int kc2 = 0; kc2 < 4; kc2++) {
#pragma unroll
                for (int half = 0; half < 2; half++) {
                    int nf = 2 * kc2 + half;
                    float e0 = ex2(s[mf][nf][0] - mnew0);
                    float e1 = ex2(s[mf][nf][1] - mnew0);
                    float e2 = ex2(s[mf][nf][2] - mnew1);
                    float e3 = ex2(s[mf][nf][3] - mnew1);
                    p[mf][kc2][2 * half]     = h2u(__float2half_rn(e0), __float2half_rn(e1));
                    p[mf][kc2][2 * half + 1] = h2u(__float2half_rn(e2), __float2half_rn(e3));
                }
            }
        }

        // l_tile = P . 1  (8 HMMA, no LDS, no shuffles)
        float lc[2][4] = {{0.0f, 0.0f, 0.0f, 0.0f}, {0.0f, 0.0f, 0.0f, 0.0f}};
#pragma unroll
        for (int mf = 0; mf < 2; mf++)
#pragma unroll
            for (int kc2 = 0; kc2 < 4; kc2++)
                mma16816(lc[mf], p[mf][kc2][0], p[mf][kc2][1],
                         p[mf][kc2][2], p[mf][kc2][3], HONE, HONE);
#pragma unroll
        for (int mf = 0; mf < 2; mf++) {
            lrun[mf][0] = lrun[mf][0] * corr[mf][0] + lc[mf][0];
            lrun[mf][1] = lrun[mf][1] * corr[mf][1] + lc[mf][2];
        }

        if (__any_sync(0xffffffffu,
                       fminf(fminf(corr[0][0], corr[0][1]),
                             fminf(corr[1][0], corr[1][1])) < 0.99999f)) {
#pragma unroll
            for (int mf = 0; mf < 2; mf++)
#pragma unroll
                for (int nf = 0; nf < 16; nf++) {
                    o[mf][nf][0] *= corr[mf][0]; o[mf][nf][1] *= corr[mf][0];
                    o[mf][nf][2] *= corr[mf][1]; o[mf][nf][3] *= corr[mf][1];
                }
        }

        CP_WAIT1();
        __syncthreads();

#pragma unroll
        for (int kc2 = 0; kc2 < 4; kc2++) {
#pragma unroll
            for (int dg = 0; dg < 8; dg++) {
                u32 v0, v1, v2, v3;
                ldm4(v0, v1, v2, v3,
                     s32 + OFF_V + SWZ128((dg * 16 + lrow) * 128 + kc2 * 32 + lcol));
#pragma unroll
                for (int mf = 0; mf < 2; mf++) {
                    mma16816(o[mf][2 * dg],
                             p[mf][kc2][0], p[mf][kc2][1], p[mf][kc2][2], p[mf][kc2][3], v0, v2);
                    mma16816(o[mf][2 * dg + 1],
                             p[mf][kc2][0], p[mf][kc2][1], p[mf][kc2][2], p[mf][kc2][3], v1, v3);
                }
            }
        }

        __syncthreads();
        if (tile + 1 < KV_TILES) load_v(s32, (tile + 1) * 64, gvt, t);
        CP_COMMIT();
    }

    float* po = g_po + ((size_t)(split * BB + b) * NP + row0 + wr) * CI;
    float* pm = g_pm + (size_t)(split * BB + b) * NP + row0 + wr;
    float* pl = g_pl + (size_t)(split * BB + b) * NP + row0 + wr;
#pragma unroll
    for (int mf = 0; mf < 2; mf++) {
        int r0 = mf * 16 + g;
#pragma unroll
        for (int nf = 0; nf < 16; nf++) {
            *(float2*)&po[(size_t)r0 * CI + nf * 8 + c2] =
                make_float2(o[mf][nf][0], o[mf][nf][1]);
            *(float2*)&po[(size_t)(r0 + 8) * CI + nf * 8 + c2] =
                make_float2(o[mf][nf][2], o[mf][nf][3]);
        }
        if ((lane & 3) == 0) {
            pm[r0] = mrun[mf][0]; pm[r0 + 8] = mrun[mf][1];
            pl[r0] = lrun[mf][0]; pl[r0 + 8] = lrun[mf][1];
        }
    }
}

// =================================================================
// Kernel 3: fused merge + output projection on tensor cores.
// =================================================================
__global__ __launch_bounds__(256, 2) void outproj_kernel(
    const float* __restrict__ x, const float* __restrict__ wb,
    float* __restrict__ out)
{
    extern __shared__ char ps[];
    __shared__ float wgt0[128], wgt1[128];
    const u32 s32 = smem_u32(ps);
    const int b  = blockIdx.z;
    const int cb = blockIdx.y * 128;
    const int n0 = blockIdx.x * 128;
    const int t  = threadIdx.x;
    const int lane = t & 31;
    const int w  = t >> 5;
    const int wm = w & 3;
    const int wn = w >> 2;
    const int lrow = lane & 15;
    const int lcol = (lane >> 4) * 16;
    const int g    = lane >> 2;
    const int c2   = (lane & 3) * 2;

    if (t < 128) {
        int bn = b * NP + n0 + t;
        float m0 = g_pm[bn], m1 = g_pm[BB * NP + bn];
        float l0 = g_pl[bn], l1 = g_pl[BB * NP + bn];
        float m  = fmaxf(m0, m1);
        float w0 = ex2(m0 - m), w1 = ex2(m1 - m);
        float inv = 1.0f / (w0 * l0 + w1 * l1);
        wgt0[t] = w0 * inv;
        wgt1[t] = w1 * inv;
    }
    __syncthreads();

    float acc[2][8][4];
#pragma unroll
    for (int mf = 0; mf < 2; mf++)
#pragma unroll
        for (int nf = 0; nf < 8; nf++)
#pragma unroll
            for (int q = 0; q < 4; q++) acc[mf][nf][q] = 0.0f;

    const float* p0 = g_po + ((size_t)b * NP + n0) * CI;
    const float* p1 = g_po + ((size_t)(BB + b) * NP + n0) * CI;

    for (int o0 = 0; o0 < CI; o0 += 64) {
        __syncthreads();
#pragma unroll
        for (int i = 0; i < 8; i++) {
            int id = i * 256 + t;
            int row = id >> 4, ch = id & 15;
            float4 a = *(const float4*)&p0[(size_t)row * CI + o0 + ch * 4];
            float4 c = *(const float4*)&p1[(size_t)row * CI + o0 + ch * 4];
            float w0 = wgt0[row], w1 = wgt1[row];
            float m[4] = {a.x * w0 + c.x * w1, a.y * w0 + c.y * w1,
                          a.z * w0 + c.z * w1, a.w * w0 + c.w * w1};
            __half h[4], l[4];
#pragma unroll
            for (int q = 0; q < 4; q++) {
                h[q] = __float2half_rn(m[q]);
                l[q] = __float2half_rn(m[q] - __half2float(h[q]));
            }
            u32 sw = SWZ128(row * 128 + ch * 8);
            *(uint2*)(ps + sw)         = make_uint2(h2u(h[0], h[1]), h2u(h[2], h[3]));
            *(uint2*)(ps + 16384 + sw) = make_uint2(h2u(l[0], l[1]), h2u(l[2], l[3]));
        }
#pragma unroll
        for (int i = 0; i < 4; i++) {
            int id = i * 256 + t;
            int row = id >> 3, ch = id & 7;
            u32 sw = SWZ128(row * 128 + ch * 16);
            cpa(s32 + 32768 + sw, g_wwh + (size_t)(cb + row) * CI + o0 + ch * 8);
            cpa(s32 + 49152 + sw, g_wwl + (size_t)(cb + row) * CI + o0 + ch * 8);
        }
        CP_COMMIT();
        CP_WAIT0();
        __syncthreads();

#pragma unroll
        for (int kc = 0; kc < 4; kc++) {
            u32 Ah[2][4], Al[2][4], B[4][4];
#pragma unroll
            for (int mf = 0; mf < 2; mf++)
                ldm4(Ah[mf][0], Ah[mf][1], Ah[mf][2], Ah[mf][3],
                     s32 + SWZ128((wm * 32 + mf * 16 + lrow) * 128 + kc * 32 + lcol));
#pragma unroll
            for (int bf = 0; bf < 4; bf++)
                ldm4(B[bf][0], B[bf][1], B[bf][2], B[bf][3],
                     s32 + 32768 + SWZ128((wn * 64 + bf * 16 + lrow) * 128 + kc * 32 + lcol));
#pragma unroll
            for (int mf = 0; mf < 2; mf++)
#pragma unroll
                for (int bf = 0; bf < 4; bf++) {
                    mma16816(acc[mf][2 * bf],     Ah[mf][0], Ah[mf][1], Ah[mf][2], Ah[mf][3], B[bf][0], B[bf][2]);
                    mma16816(acc[mf][2 * bf + 1], Ah[mf][0], Ah[mf][1], Ah[mf][2], Ah[mf][3], B[bf][1], B[bf][3]);
                }
#pragma unroll
            for (int mf = 0; mf < 2; mf++)
                ldm4(Al[mf][0], Al[mf][1], Al[mf][2], Al[mf][3],
                     s32 + 16384 + SWZ128((wm * 32 + mf * 16 + lrow) * 128 + kc * 32 + lcol));
#pragma unroll
            for (int mf = 0; mf < 2; mf++)
#pragma unroll
                for (int bf = 0; bf < 4; bf++) {
                    mma16816(acc[mf][2 * bf],     Al[mf][0], Al[mf][1], Al[mf][2], Al[mf][3], B[bf][0], B[bf][2]);
                    mma16816(acc[mf][2 * bf + 1], Al[mf][0], Al[mf][1], Al[mf][2], Al[mf][3], B[bf][1], B[bf][3]);
                }
#pragma unroll
            for (int bf = 0; bf < 4; bf++)
                ldm4(B[bf][0], B[bf][1], B[bf][2], B[bf][3],
                     s32 + 49152 + SWZ128((wn * 64 + bf * 16 + lrow) * 128 + kc * 32 + lcol));
#pragma unroll
            for (int mf = 0; mf < 2; mf++)
#pragma unroll
                for (int bf = 0; bf < 4; bf++) {
                    mma16816(acc[mf][2 * bf],     Ah[mf][0], Ah[mf][1], Ah[mf][2], Ah[mf][3], B[bf][0], B[bf][2]);
                    mma16816(acc[mf][2 * bf + 1], Ah[mf][0], Ah[mf][1], Ah[mf][2], Ah[mf][3], B[bf][1], B[bf][3]);
                }
        }
    }
    __syncthreads();

#pragma unroll
    for (int mf = 0; mf < 2; mf++) {
        int nl = wm * 32 + mf * 16 + g;
#pragma unroll
        for (int nf = 0; nf < 8; nf++) {
            int cl = wn * 64 + nf * 8 + c2;
            *(float*)(ps + (cl * 128 + nl) * 4)           = acc[mf][nf][0];
            *(float*)(ps + ((cl + 1) * 128 + nl) * 4)     = acc[mf][nf][1];
            *(float*)(ps + (cl * 128 + nl + 8) * 4)       = acc[mf][nf][2];
            *(float*)(ps + ((cl + 1) * 128 + nl + 8) * 4) = acc[mf][nf][3];
        }
    }
    __syncthreads();

    int r = t >> 1, part = t & 1;
    float bv = wb[cb + r];
    size_t base = ((size_t)b * CC + cb + r) * NP + n0 + part * 64;
#pragma unroll
    for (int k = 0; k < 16; k++) {
        float4 v  = *(float4*)(ps + (r * 128 + part * 64 + k * 4) * 4);
        float4 xv = *(const float4*)&x[base + k * 4];
        float4 rr = make_float4(v.x + bv + xv.x, v.y + bv + xv.y,
                                v.z + bv + xv.z, v.w + bv + xv.w);
        *(float4*)&out[base + k * 4] = rr;
    }
}

// =================================================================
extern "C" void kernel_launch(void* const* d_in, const int* in_sizes, int n_in,
                              void* d_out, int out_size)
{
    const float* x  = (const float*)d_in[0];
    const float* tw = (const float*)d_in[1];
    const float* tb = (const float*)d_in[2];
    const float* pw = (const float*)d_in[3];
    const float* pb = (const float*)d_in[4];
    const float* gw = (const float*)d_in[5];
    const float* gb = (const float*)d_in[6];
    const float* ww = (const float*)d_in[7];
    const float* wb = (const float*)d_in[8];
    float* out = (float*)d_out;

    cudaFuncSetAttribute(attn_kernel,    cudaFuncAttributeMaxDynamicSharedMemorySize, SMEM_ATTN);
    cudaFuncSetAttribute(proj_kernel,    cudaFuncAttributeMaxDynamicSharedMemorySize, PJ_SMEM);
    cudaFuncSetAttribute(outproj_kernel, cudaFuncAttributeMaxDynamicSharedMemorySize, PJ_SMEM);

    conv_all<<<4096 + 128, 256>>>(x, tw, pw, gw, ww);
    proj_kernel<<<dim3(NP / 128, BB, 3), 256, PJ_SMEM>>>(tb, pb, gb);
    attn_kernel<<<dim3(NP / 128, 2, BB), 128, SMEM_ATTN>>>();
    outproj_kernel<<<dim3(NP / 128, CC / 128, BB), 256, PJ_SMEM>>>(x, wb, out);
}